// round 1
// baseline (speedup 1.0000x reference)
#include <cuda_runtime.h>
#include <math.h>

#define S_LEN  2048
#define DMODEL 1024
#define NHEAD  16
#define DK     64
#define B_SZ   2
#define M_TOT  (B_SZ * S_LEN)      // 4096
#define BH_TOT (B_SZ * NHEAD)      // 32

// ------------------------- scratch (device globals; no allocs allowed) ------
__device__ float g_Q[(size_t)BH_TOT * S_LEN * DK];   // [b,h,s,dk]
__device__ float g_K[(size_t)BH_TOT * S_LEN * DK];
__device__ float g_V[(size_t)BH_TOT * S_LEN * DK];
__device__ float g_O[(size_t)M_TOT * DMODEL];        // [b,s,d]

// ------------------------- GEMM: C[m,n] = sum_k A[m,k] * W[n,k] -------------
// modes: 0 = final projection (A = g_O internally, write out[m,n])
//        1 = V projection  (write g_V in [b,h,s,dk])
//        2 = Q projection  (RoPE, write g_Q)
//        3 = K projection  (RoPE, write g_K)
#define BM 128
#define BN 64
#define BK 16
#define AP (BM + 4)   // 132, smem pitch for A (float4-aligned, conflict-free)
#define BP (BN + 4)   // 68

__global__ __launch_bounds__(256) void gemm_kernel(
    const float* __restrict__ A, const float* __restrict__ W,
    float* __restrict__ out, int mode)
{
    const int K = DMODEL, N = DMODEL;
    const float* Ap = (mode == 0) ? g_O : A;

    __shared__ float As[BK][AP];
    __shared__ float Bs[BK][BP];

    const int bm = blockIdx.y * BM;
    const int bn = blockIdx.x * BN;
    const int tid = threadIdx.x;
    const int ty = tid >> 4;          // 0..15
    const int tx = tid & 15;          // 0..15
    const int row0 = ty * 8;
    const int col0 = tx * 4;

    float acc[8][4];
    #pragma unroll
    for (int i = 0; i < 8; i++)
        #pragma unroll
        for (int j = 0; j < 4; j++) acc[i][j] = 0.f;

    for (int k0 = 0; k0 < K; k0 += BK) {
        // A tile: 128x16 = 512 float4, 2 per thread
        #pragma unroll
        for (int it = 0; it < 2; it++) {
            int f = tid + it * 256;
            int r = f >> 2, kq = f & 3;
            float4 v = *(const float4*)(Ap + (size_t)(bm + r) * K + k0 + kq * 4);
            As[kq * 4 + 0][r] = v.x; As[kq * 4 + 1][r] = v.y;
            As[kq * 4 + 2][r] = v.z; As[kq * 4 + 3][r] = v.w;
        }
        // B tile: 64x16 = 256 float4, 1 per thread
        {
            int r = tid >> 2, kq = tid & 3;
            float4 v = *(const float4*)(W + (size_t)(bn + r) * K + k0 + kq * 4);
            Bs[kq * 4 + 0][r] = v.x; Bs[kq * 4 + 1][r] = v.y;
            Bs[kq * 4 + 2][r] = v.z; Bs[kq * 4 + 3][r] = v.w;
        }
        __syncthreads();

        #pragma unroll
        for (int kk = 0; kk < BK; kk++) {
            float a[8], b[4];
            *(float4*)(a)     = *(const float4*)&As[kk][row0];
            *(float4*)(a + 4) = *(const float4*)&As[kk][row0 + 4];
            *(float4*)(b)     = *(const float4*)&Bs[kk][col0];
            #pragma unroll
            for (int i = 0; i < 8; i++)
                #pragma unroll
                for (int j = 0; j < 4; j++)
                    acc[i][j] = fmaf(a[i], b[j], acc[i][j]);
        }
        __syncthreads();
    }

    // ------------------- epilogue -------------------
    if (mode == 0) {
        #pragma unroll
        for (int i = 0; i < 8; i++) {
            int m = bm + row0 + i;
            float4 v = make_float4(acc[i][0], acc[i][1], acc[i][2], acc[i][3]);
            *(float4*)(out + (size_t)m * N + bn + col0) = v;
        }
        return;
    }

    const int gn = bn + col0;
    const int h = gn >> 6;
    const int dcol = gn & 63;               // multiple of 4 -> pairs self-contained
    float* dst = (mode == 1) ? g_V : (mode == 2 ? g_Q : g_K);

    if (mode == 1) {
        #pragma unroll
        for (int i = 0; i < 8; i++) {
            int m = bm + row0 + i;
            int b = m >> 11, s = m & 2047;
            float4 v = make_float4(acc[i][0], acc[i][1], acc[i][2], acc[i][3]);
            *(float4*)(dst + ((size_t)(b * NHEAD + h) * S_LEN + s) * DK + dcol) = v;
        }
    } else {
        // RoPE: pair p -> freq = theta^(-2p/dk) = exp(-p * ln(10000)/32)
        const int p0 = dcol >> 1;
        const float kf = 0.28782313662425573f;   // ln(10000)/32
        const float f0 = expf(-(float)p0 * kf);
        const float f1 = expf(-(float)(p0 + 1) * kf);
        #pragma unroll
        for (int i = 0; i < 8; i++) {
            int m = bm + row0 + i;
            int b = m >> 11, s = m & 2047;
            float fs = (float)s;
            float c0, s0, c1, s1;
            sincosf(fs * f0, &s0, &c0);
            sincosf(fs * f1, &s1, &c1);
            float e0 = acc[i][0], o0 = acc[i][1];
            float e1 = acc[i][2], o1 = acc[i][3];
            float4 v = make_float4(e0 * c0 - o0 * s0, e0 * s0 + o0 * c0,
                                   e1 * c1 - o1 * s1, e1 * s1 + o1 * c1);
            *(float4*)(dst + ((size_t)(b * NHEAD + h) * S_LEN + s) * DK + dcol) = v;
        }
    }
}

// ------------------------- causal flash attention ---------------------------
// grid (32 q-tiles, 32 bh), 256 threads. Br=Bc=64, dk=64.
#define FP 65
#define FLASH_SMEM (4 * 64 * FP * 4)   // Qs,Ks,Vs,Ps = 66560 bytes

__global__ __launch_bounds__(256) void flash_kernel()
{
    extern __shared__ float sm[];
    float* Qs = sm;
    float* Ks = sm + 64 * FP;
    float* Vs = sm + 2 * 64 * FP;
    float* Ps = sm + 3 * 64 * FP;

    const int qt = blockIdx.x;
    const int bh = blockIdx.y;
    const float* Qp = g_Q + (size_t)bh * S_LEN * DK;
    const float* Kp = g_K + (size_t)bh * S_LEN * DK;
    const float* Vp = g_V + (size_t)bh * S_LEN * DK;

    const int tid = threadIdx.x;
    const int rg = tid >> 4, cg = tid & 15;
    const int r0 = rg * 4, c0 = cg * 4;

    // load Q tile (64x64)
    for (int f = tid; f < 64 * 16; f += 256) {
        int r = f >> 4, q = f & 15;
        float4 v = *(const float4*)(Qp + (size_t)(qt * 64 + r) * DK + q * 4);
        Qs[r * FP + q * 4 + 0] = v.x; Qs[r * FP + q * 4 + 1] = v.y;
        Qs[r * FP + q * 4 + 2] = v.z; Qs[r * FP + q * 4 + 3] = v.w;
    }

    float mi[4] = {-INFINITY, -INFINITY, -INFINITY, -INFINITY};
    float li[4] = {0.f, 0.f, 0.f, 0.f};
    float acc[4][4];
    #pragma unroll
    for (int i = 0; i < 4; i++)
        #pragma unroll
        for (int j = 0; j < 4; j++) acc[i][j] = 0.f;

    for (int kt = 0; kt <= qt; kt++) {
        __syncthreads();   // Q ready (iter 0); prior Vs/Ps reads done
        for (int f = tid; f < 64 * 16; f += 256) {
            int r = f >> 4, q = f & 15;
            float4 kv = *(const float4*)(Kp + (size_t)(kt * 64 + r) * DK + q * 4);
            Ks[r * FP + q * 4 + 0] = kv.x; Ks[r * FP + q * 4 + 1] = kv.y;
            Ks[r * FP + q * 4 + 2] = kv.z; Ks[r * FP + q * 4 + 3] = kv.w;
            float4 vv = *(const float4*)(Vp + (size_t)(kt * 64 + r) * DK + q * 4);
            Vs[r * FP + q * 4 + 0] = vv.x; Vs[r * FP + q * 4 + 1] = vv.y;
            Vs[r * FP + q * 4 + 2] = vv.z; Vs[r * FP + q * 4 + 3] = vv.w;
        }
        __syncthreads();

        // S = Q K^T (4x4 per thread)
        float sc[4][4];
        #pragma unroll
        for (int i = 0; i < 4; i++)
            #pragma unroll
            for (int j = 0; j < 4; j++) sc[i][j] = 0.f;
        #pragma unroll 8
        for (int k = 0; k < 64; k++) {
            float a0 = Qs[(r0 + 0) * FP + k], a1 = Qs[(r0 + 1) * FP + k];
            float a2 = Qs[(r0 + 2) * FP + k], a3 = Qs[(r0 + 3) * FP + k];
            float b0 = Ks[(c0 + 0) * FP + k], b1 = Ks[(c0 + 1) * FP + k];
            float b2 = Ks[(c0 + 2) * FP + k], b3 = Ks[(c0 + 3) * FP + k];
            sc[0][0] = fmaf(a0, b0, sc[0][0]); sc[0][1] = fmaf(a0, b1, sc[0][1]);
            sc[0][2] = fmaf(a0, b2, sc[0][2]); sc[0][3] = fmaf(a0, b3, sc[0][3]);
            sc[1][0] = fmaf(a1, b0, sc[1][0]); sc[1][1] = fmaf(a1, b1, sc[1][1]);
            sc[1][2] = fmaf(a1, b2, sc[1][2]); sc[1][3] = fmaf(a1, b3, sc[1][3]);
            sc[2][0] = fmaf(a2, b0, sc[2][0]); sc[2][1] = fmaf(a2, b1, sc[2][1]);
            sc[2][2] = fmaf(a2, b2, sc[2][2]); sc[2][3] = fmaf(a2, b3, sc[2][3]);
            sc[3][0] = fmaf(a3, b0, sc[3][0]); sc[3][1] = fmaf(a3, b1, sc[3][1]);
            sc[3][2] = fmaf(a3, b2, sc[3][2]); sc[3][3] = fmaf(a3, b3, sc[3][3]);
        }
        #pragma unroll
        for (int i = 0; i < 4; i++)
            #pragma unroll
            for (int j = 0; j < 4; j++) sc[i][j] *= 0.125f;   // 1/sqrt(64)

        if (kt == qt) {   // diagonal tile: mask cols > row
            #pragma unroll
            for (int i = 0; i < 4; i++)
                #pragma unroll
                for (int j = 0; j < 4; j++)
                    if (c0 + j > r0 + i) sc[i][j] = -INFINITY;
        }

        // online softmax (rows owned by 16-lane groups: same rg = same half-warp)
        float rmax[4], rsum[4];
        #pragma unroll
        for (int i = 0; i < 4; i++) {
            float mx = fmaxf(fmaxf(sc[i][0], sc[i][1]), fmaxf(sc[i][2], sc[i][3]));
            #pragma unroll
            for (int off = 8; off > 0; off >>= 1)
                mx = fmaxf(mx, __shfl_xor_sync(0xffffffffu, mx, off, 16));
            rmax[i] = mx;
        }
        #pragma unroll
        for (int i = 0; i < 4; i++) {
            float mnew = fmaxf(mi[i], rmax[i]);
            float su = 0.f;
            #pragma unroll
            for (int j = 0; j < 4; j++) {
                float p = expf(sc[i][j] - mnew);
                sc[i][j] = p;
                su += p;
            }
            #pragma unroll
            for (int off = 8; off > 0; off >>= 1)
                su += __shfl_xor_sync(0xffffffffu, su, off, 16);
            float psc = expf(mi[i] - mnew);      // 0 when mi = -inf
            li[i] = li[i] * psc + su;
            mi[i] = mnew;
            #pragma unroll
            for (int j = 0; j < 4; j++) acc[i][j] *= psc;
            rsum[i] = su; (void)rsum;
        }

        // stage P (row group written/read by the same 16-lane half-warp)
        #pragma unroll
        for (int i = 0; i < 4; i++)
            #pragma unroll
            for (int j = 0; j < 4; j++)
                Ps[(r0 + i) * FP + c0 + j] = sc[i][j];
        __syncwarp();

        // O += P V  (thread: rows r0..r0+3, d-cols c0..c0+3)
        #pragma unroll 8
        for (int c = 0; c < 64; c++) {
            float p0 = Ps[(r0 + 0) * FP + c], p1 = Ps[(r0 + 1) * FP + c];
            float p2 = Ps[(r0 + 2) * FP + c], p3 = Ps[(r0 + 3) * FP + c];
            float v0 = Vs[c * FP + c0 + 0], v1 = Vs[c * FP + c0 + 1];
            float v2 = Vs[c * FP + c0 + 2], v3 = Vs[c * FP + c0 + 3];
            acc[0][0] = fmaf(p0, v0, acc[0][0]); acc[0][1] = fmaf(p0, v1, acc[0][1]);
            acc[0][2] = fmaf(p0, v2, acc[0][2]); acc[0][3] = fmaf(p0, v3, acc[0][3]);
            acc[1][0] = fmaf(p1, v0, acc[1][0]); acc[1][1] = fmaf(p1, v1, acc[1][1]);
            acc[1][2] = fmaf(p1, v2, acc[1][2]); acc[1][3] = fmaf(p1, v3, acc[1][3]);
            acc[2][0] = fmaf(p2, v0, acc[2][0]); acc[2][1] = fmaf(p2, v1, acc[2][1]);
            acc[2][2] = fmaf(p2, v2, acc[2][2]); acc[2][3] = fmaf(p2, v3, acc[2][3]);
            acc[3][0] = fmaf(p3, v0, acc[3][0]); acc[3][1] = fmaf(p3, v1, acc[3][1]);
            acc[3][2] = fmaf(p3, v2, acc[3][2]); acc[3][3] = fmaf(p3, v3, acc[3][3]);
        }
    }

    // write O in [b,s,d] layout for the final GEMM
    const int b = bh >> 4, h = bh & 15;
    #pragma unroll
    for (int i = 0; i < 4; i++) {
        int srow = qt * 64 + r0 + i;
        float inv = 1.f / li[i];
        #pragma unroll
        for (int j = 0; j < 4; j++)
            g_O[((size_t)(b * S_LEN + srow)) * DMODEL + h * DK + c0 + j] = acc[i][j] * inv;
    }
}

// ------------------------- launch -------------------------------------------
extern "C" void kernel_launch(void* const* d_in, const int* in_sizes, int n_in,
                              void* d_out, int out_size)
{
    const float* x  = (const float*)d_in[0];
    const float* Wq = (const float*)d_in[1];
    const float* Wk = (const float*)d_in[2];
    const float* Wv = (const float*)d_in[3];
    const float* Wo = (const float*)d_in[4];
    float* out = (float*)d_out;

    cudaFuncSetAttribute(flash_kernel, cudaFuncAttributeMaxDynamicSharedMemorySize,
                         FLASH_SMEM);

    dim3 ggrid(DMODEL / BN, M_TOT / BM);   // (16, 32)
    gemm_kernel<<<ggrid, 256>>>(x, Wq, nullptr, 2);   // Q + RoPE
    gemm_kernel<<<ggrid, 256>>>(x, Wk, nullptr, 3);   // K + RoPE
    gemm_kernel<<<ggrid, 256>>>(x, Wv, nullptr, 1);   // V

    dim3 fgrid(S_LEN / 64, BH_TOT);        // (32, 32)
    flash_kernel<<<fgrid, 256, FLASH_SMEM>>>();

    gemm_kernel<<<ggrid, 256>>>(nullptr, Wo, out, 0); // output projection
}

// round 3
// speedup vs baseline: 1.6393x; 1.6393x over previous
#include <cuda_runtime.h>
#include <math.h>
#include <stdint.h>

#define S_LEN  2048
#define DMODEL 1024
#define NHEAD  16
#define DK     64
#define B_SZ   2
#define M_TOT  (B_SZ * S_LEN)      // 4096
#define BH_TOT (B_SZ * NHEAD)      // 32

// ------------------------- scratch (device globals; no allocs allowed) ------
__device__ float g_Q[(size_t)BH_TOT * S_LEN * DK];   // [b,h,s,dk]
__device__ float g_K[(size_t)BH_TOT * S_LEN * DK];
__device__ float g_V[(size_t)BH_TOT * S_LEN * DK];
__device__ float g_O[(size_t)M_TOT * DMODEL];        // [b,s,d]

// ======================= helpers =============================================
__device__ __forceinline__ uint32_t smem_u32(const void* p) {
    uint32_t a;
    asm("{ .reg .u64 t; cvta.to.shared.u64 t, %1; cvt.u32.u64 %0, t; }"
        : "=r"(a) : "l"(p));
    return a;
}
__device__ __forceinline__ uint32_t f32_to_tf32(float f) {
    uint32_t r;
    asm("cvt.rna.tf32.f32 %0, %1;" : "=r"(r) : "f"(f));
    return r;
}
__device__ __forceinline__ void ldsm4(uint32_t r[4], uint32_t addr) {
    asm volatile("ldmatrix.sync.aligned.m8n8.x4.shared.b16 {%0,%1,%2,%3}, [%4];"
                 : "=r"(r[0]), "=r"(r[1]), "=r"(r[2]), "=r"(r[3]) : "r"(addr));
}
__device__ __forceinline__ void mma_tf32(float d[4], const uint32_t a[4],
                                         const uint32_t b[2]) {
    asm volatile("mma.sync.aligned.m16n8k8.row.col.f32.tf32.tf32.f32 "
                 "{%0,%1,%2,%3}, {%4,%5,%6,%7}, {%8,%9}, {%0,%1,%2,%3};"
                 : "+f"(d[0]), "+f"(d[1]), "+f"(d[2]), "+f"(d[3])
                 : "r"(a[0]), "r"(a[1]), "r"(a[2]), "r"(a[3]),
                   "r"(b[0]), "r"(b[1]));
}

// ======================= tf32 GEMM via mma.sync ==============================
// C[m,n] = sum_k A[m,k] * W[n,k], M=4096, N=K=1024.
// Tile 128x128, BK=32. 8 warps (2m x 4n), warp tile 64x32.
// modes: 0 = final proj (A = g_O, write out); 1 = V; 2 = Q+RoPE; 3 = K+RoPE.
#define PA 36                        // smem pitch in floats (bank-staggered)
#define GSMEM (2 * 128 * PA * 4)     // 36864 bytes

__global__ __launch_bounds__(256) void gemm_tf32_kernel(
    const float* __restrict__ A, const float* __restrict__ W,
    float* __restrict__ out, int mode)
{
    extern __shared__ float sm[];
    float* As = sm;                  // [128 m][32 k] pitch PA (tf32 bits)
    float* Bs = sm + 128 * PA;       // [128 n][32 k] pitch PA
    const uint32_t sA = smem_u32(As);

    const float* Ap = (mode == 0) ? g_O : A;
    const int tid = threadIdx.x;
    const int wid = tid >> 5, lane = tid & 31;
    const int wm = (wid >> 2) * 64;          // warp m offset: 0 / 64
    const int wn = (wid & 3) * 32;           // warp n offset: 0/32/64/96
    const int bm = blockIdx.y * 128;
    const int bn = blockIdx.x * 128;

    // ldmatrix quadrant address (per lane, constant across loop):
    const int q = lane >> 3, rq = lane & 7;
    const int qm = (q & 1) * 8, qk = (q & 2) * 2;   // q>=2 -> k+4

    float acc[4][4][4];                       // [mt][nt][reg]
    #pragma unroll
    for (int mt = 0; mt < 4; mt++)
        #pragma unroll
        for (int nt = 0; nt < 4; nt++)
            #pragma unroll
            for (int i = 0; i < 4; i++) acc[mt][nt][i] = 0.f;

    float4 av[4], bv[4];
    // prologue: ldg k-tile 0
    #pragma unroll
    for (int i = 0; i < 4; i++) {
        int f = tid + i * 256, r = f >> 3, c = f & 7;
        av[i] = *(const float4*)(Ap + (size_t)(bm + r) * DMODEL + c * 4);
        bv[i] = *(const float4*)(W  + (size_t)(bn + r) * DMODEL + c * 4);
    }

    for (int t = 0; t < 32; t++) {
        // stage regs -> smem (cvt to tf32)
        #pragma unroll
        for (int i = 0; i < 4; i++) {
            int f = tid + i * 256, r = f >> 3, c = f & 7;
            uint32_t off = (uint32_t)(r * PA + c * 4) * 4;
            asm volatile("st.shared.v4.b32 [%0], {%1, %2, %3, %4};"
                :: "r"(sA + off),
                   "r"(f32_to_tf32(av[i].x)), "r"(f32_to_tf32(av[i].y)),
                   "r"(f32_to_tf32(av[i].z)), "r"(f32_to_tf32(av[i].w)) : "memory");
            asm volatile("st.shared.v4.b32 [%0], {%1, %2, %3, %4};"
                :: "r"(sA + (uint32_t)(128 * PA * 4) + off),
                   "r"(f32_to_tf32(bv[i].x)), "r"(f32_to_tf32(bv[i].y)),
                   "r"(f32_to_tf32(bv[i].z)), "r"(f32_to_tf32(bv[i].w)) : "memory");
        }
        __syncthreads();
        if (t < 31) {   // prefetch next k-tile while computing on this one
            int k0 = (t + 1) * 32;
            #pragma unroll
            for (int i = 0; i < 4; i++) {
                int f = tid + i * 256, r = f >> 3, c = f & 7;
                av[i] = *(const float4*)(Ap + (size_t)(bm + r) * DMODEL + k0 + c * 4);
                bv[i] = *(const float4*)(W  + (size_t)(bn + r) * DMODEL + k0 + c * 4);
            }
        }
        #pragma unroll
        for (int ks = 0; ks < 4; ks++) {
            uint32_t aR[4][4], bR[4][2];
            #pragma unroll
            for (int mt = 0; mt < 4; mt++) {
                uint32_t off = (uint32_t)((wm + mt * 16 + qm + rq) * PA +
                                          ks * 8 + qk) * 4;
                ldsm4(aR[mt], sA + off);
            }
            #pragma unroll
            for (int nt = 0; nt < 4; nt++) {
                const float* bp = Bs + (wn + nt * 8 + (lane >> 2)) * PA +
                                  ks * 8 + (lane & 3);
                bR[nt][0] = __float_as_uint(bp[0]);
                bR[nt][1] = __float_as_uint(bp[4]);
            }
            #pragma unroll
            for (int mt = 0; mt < 4; mt++)
                #pragma unroll
                for (int nt = 0; nt < 4; nt++)
                    mma_tf32(acc[mt][nt], aR[mt], bR[nt]);
        }
        __syncthreads();
    }

    // ---------------- epilogue ------------------------------------------------
    const float kf = 0.28782313662425573f;   // ln(10000)/32
    #pragma unroll
    for (int mt = 0; mt < 4; mt++) {
        #pragma unroll
        for (int nt = 0; nt < 4; nt++) {
            float* a = acc[mt][nt];
            const int col = bn + wn + nt * 8 + 2 * (lane & 3);
            const int rbase = bm + wm + mt * 16 + (lane >> 2);
            if (mode == 0) {
                *(float2*)(out + (size_t)rbase * DMODEL + col) =
                    make_float2(a[0], a[1]);
                *(float2*)(out + (size_t)(rbase + 8) * DMODEL + col) =
                    make_float2(a[2], a[3]);
            } else {
                const int h = col >> 6, d = col & 63;
                float* dst = (mode == 1) ? g_V : (mode == 2 ? g_Q : g_K);
                float fr = 0.f;
                if (mode != 1) fr = expf(-(float)(d >> 1) * kf);
                #pragma unroll
                for (int rr = 0; rr < 2; rr++) {
                    int m = rbase + rr * 8;
                    int b = m >> 11, s = m & 2047;
                    float e = a[rr * 2], o = a[rr * 2 + 1];
                    float2 v;
                    if (mode == 1) {
                        v = make_float2(e, o);
                    } else {
                        float sn, cs;
                        sincosf((float)s * fr, &sn, &cs);
                        v = make_float2(e * cs - o * sn, e * sn + o * cs);
                    }
                    *(float2*)(dst + ((size_t)(b * NHEAD + h) * S_LEN + s) * DK + d) = v;
                }
            }
        }
    }
}

// ------------------------- causal flash attention (fp32) --------------------
#define FP 65
#define FLASH_SMEM (4 * 64 * FP * 4)   // 66560 bytes

__global__ __launch_bounds__(256) void flash_kernel()
{
    extern __shared__ float smf[];
    float* Qs = smf;
    float* Ks = smf + 64 * FP;
    float* Vs = smf + 2 * 64 * FP;
    float* Ps = smf + 3 * 64 * FP;

    const int qt = blockIdx.x;
    const int bh = blockIdx.y;
    const float* Qp = g_Q + (size_t)bh * S_LEN * DK;
    const float* Kp = g_K + (size_t)bh * S_LEN * DK;
    const float* Vp = g_V + (size_t)bh * S_LEN * DK;

    const int tid = threadIdx.x;
    const int rg = tid >> 4, cg = tid & 15;
    const int r0 = rg * 4, c0 = cg * 4;

    for (int f = tid; f < 64 * 16; f += 256) {
        int r = f >> 4, q = f & 15;
        float4 v = *(const float4*)(Qp + (size_t)(qt * 64 + r) * DK + q * 4);
        Qs[r * FP + q * 4 + 0] = v.x; Qs[r * FP + q * 4 + 1] = v.y;
        Qs[r * FP + q * 4 + 2] = v.z; Qs[r * FP + q * 4 + 3] = v.w;
    }

    float mi[4] = {-INFINITY, -INFINITY, -INFINITY, -INFINITY};
    float li[4] = {0.f, 0.f, 0.f, 0.f};
    float acc[4][4];
    #pragma unroll
    for (int i = 0; i < 4; i++)
        #pragma unroll
        for (int j = 0; j < 4; j++) acc[i][j] = 0.f;

    for (int kt = 0; kt <= qt; kt++) {
        __syncthreads();
        for (int f = tid; f < 64 * 16; f += 256) {
            int r = f >> 4, q = f & 15;
            float4 kv = *(const float4*)(Kp + (size_t)(kt * 64 + r) * DK + q * 4);
            Ks[r * FP + q * 4 + 0] = kv.x; Ks[r * FP + q * 4 + 1] = kv.y;
            Ks[r * FP + q * 4 + 2] = kv.z; Ks[r * FP + q * 4 + 3] = kv.w;
            float4 vv = *(const float4*)(Vp + (size_t)(kt * 64 + r) * DK + q * 4);
            Vs[r * FP + q * 4 + 0] = vv.x; Vs[r * FP + q * 4 + 1] = vv.y;
            Vs[r * FP + q * 4 + 2] = vv.z; Vs[r * FP + q * 4 + 3] = vv.w;
        }
        __syncthreads();

        float sc[4][4];
        #pragma unroll
        for (int i = 0; i < 4; i++)
            #pragma unroll
            for (int j = 0; j < 4; j++) sc[i][j] = 0.f;
        #pragma unroll 8
        for (int k = 0; k < 64; k++) {
            float a0 = Qs[(r0 + 0) * FP + k], a1 = Qs[(r0 + 1) * FP + k];
            float a2 = Qs[(r0 + 2) * FP + k], a3 = Qs[(r0 + 3) * FP + k];
            float b0 = Ks[(c0 + 0) * FP + k], b1 = Ks[(c0 + 1) * FP + k];
            float b2 = Ks[(c0 + 2) * FP + k], b3 = Ks[(c0 + 3) * FP + k];
            sc[0][0] = fmaf(a0, b0, sc[0][0]); sc[0][1] = fmaf(a0, b1, sc[0][1]);
            sc[0][2] = fmaf(a0, b2, sc[0][2]); sc[0][3] = fmaf(a0, b3, sc[0][3]);
            sc[1][0] = fmaf(a1, b0, sc[1][0]); sc[1][1] = fmaf(a1, b1, sc[1][1]);
            sc[1][2] = fmaf(a1, b2, sc[1][2]); sc[1][3] = fmaf(a1, b3, sc[1][3]);
            sc[2][0] = fmaf(a2, b0, sc[2][0]); sc[2][1] = fmaf(a2, b1, sc[2][1]);
            sc[2][2] = fmaf(a2, b2, sc[2][2]); sc[2][3] = fmaf(a2, b3, sc[2][3]);
            sc[3][0] = fmaf(a3, b0, sc[3][0]); sc[3][1] = fmaf(a3, b1, sc[3][1]);
            sc[3][2] = fmaf(a3, b2, sc[3][2]); sc[3][3] = fmaf(a3, b3, sc[3][3]);
        }
        #pragma unroll
        for (int i = 0; i < 4; i++)
            #pragma unroll
            for (int j = 0; j < 4; j++) sc[i][j] *= 0.125f;

        if (kt == qt) {
            #pragma unroll
            for (int i = 0; i < 4; i++)
                #pragma unroll
                for (int j = 0; j < 4; j++)
                    if (c0 + j > r0 + i) sc[i][j] = -INFINITY;
        }

        float rmax[4];
        #pragma unroll
        for (int i = 0; i < 4; i++) {
            float mx = fmaxf(fmaxf(sc[i][0], sc[i][1]), fmaxf(sc[i][2], sc[i][3]));
            #pragma unroll
            for (int off = 8; off > 0; off >>= 1)
                mx = fmaxf(mx, __shfl_xor_sync(0xffffffffu, mx, off, 16));
            rmax[i] = mx;
        }
        #pragma unroll
        for (int i = 0; i < 4; i++) {
            float mnew = fmaxf(mi[i], rmax[i]);
            float su = 0.f;
            #pragma unroll
            for (int j = 0; j < 4; j++) {
                float p = expf(sc[i][j] - mnew);
                sc[i][j] = p;
                su += p;
            }
            #pragma unroll
            for (int off = 8; off > 0; off >>= 1)
                su += __shfl_xor_sync(0xffffffffu, su, off, 16);
            float psc = expf(mi[i] - mnew);
            li[i] = li[i] * psc + su;
            mi[i] = mnew;
            #pragma unroll
            for (int j = 0; j < 4; j++) acc[i][j] *= psc;
        }

        #pragma unroll
        for (int i = 0; i < 4; i++)
            #pragma unroll
            for (int j = 0; j < 4; j++)
                Ps[(r0 + i) * FP + c0 + j] = sc[i][j];
        __syncwarp();

        #pragma unroll 8
        for (int c = 0; c < 64; c++) {
            float p0 = Ps[(r0 + 0) * FP + c], p1 = Ps[(r0 + 1) * FP + c];
            float p2 = Ps[(r0 + 2) * FP + c], p3 = Ps[(r0 + 3) * FP + c];
            float v0 = Vs[c * FP + c0 + 0], v1 = Vs[c * FP + c0 + 1];
            float v2 = Vs[c * FP + c0 + 2], v3 = Vs[c * FP + c0 + 3];
            acc[0][0] = fmaf(p0, v0, acc[0][0]); acc[0][1] = fmaf(p0, v1, acc[0][1]);
            acc[0][2] = fmaf(p0, v2, acc[0][2]); acc[0][3] = fmaf(p0, v3, acc[0][3]);
            acc[1][0] = fmaf(p1, v0, acc[1][0]); acc[1][1] = fmaf(p1, v1, acc[1][1]);
            acc[1][2] = fmaf(p1, v2, acc[1][2]); acc[1][3] = fmaf(p1, v3, acc[1][3]);
            acc[2][0] = fmaf(p2, v0, acc[2][0]); acc[2][1] = fmaf(p2, v1, acc[2][1]);
            acc[2][2] = fmaf(p2, v2, acc[2][2]); acc[2][3] = fmaf(p2, v3, acc[2][3]);
            acc[3][0] = fmaf(p3, v0, acc[3][0]); acc[3][1] = fmaf(p3, v1, acc[3][1]);
            acc[3][2] = fmaf(p3, v2, acc[3][2]); acc[3][3] = fmaf(p3, v3, acc[3][3]);
        }
    }

    const int b = bh >> 4, h = bh & 15;
    #pragma unroll
    for (int i = 0; i < 4; i++) {
        int srow = qt * 64 + r0 + i;
        float inv = 1.f / li[i];
        #pragma unroll
        for (int j = 0; j < 4; j++)
            g_O[((size_t)(b * S_LEN + srow)) * DMODEL + h * DK + c0 + j] = acc[i][j] * inv;
    }
}

// ------------------------- launch -------------------------------------------
extern "C" void kernel_launch(void* const* d_in, const int* in_sizes, int n_in,
                              void* d_out, int out_size)
{
    const float* x  = (const float*)d_in[0];
    const float* Wq = (const float*)d_in[1];
    const float* Wk = (const float*)d_in[2];
    const float* Wv = (const float*)d_in[3];
    const float* Wo = (const float*)d_in[4];
    float* out = (float*)d_out;

    cudaFuncSetAttribute(flash_kernel,
                         cudaFuncAttributeMaxDynamicSharedMemorySize, FLASH_SMEM);

    dim3 ggrid(DMODEL / 128, M_TOT / 128);   // (8, 32)
    gemm_tf32_kernel<<<ggrid, 256, GSMEM>>>(x, Wq, nullptr, 2);   // Q + RoPE
    gemm_tf32_kernel<<<ggrid, 256, GSMEM>>>(x, Wk, nullptr, 3);   // K + RoPE
    gemm_tf32_kernel<<<ggrid, 256, GSMEM>>>(x, Wv, nullptr, 1);   // V

    dim3 fgrid(S_LEN / 64, BH_TOT);          // (32, 32)
    flash_kernel<<<fgrid, 256, FLASH_SMEM>>>();

    gemm_tf32_kernel<<<ggrid, 256, GSMEM>>>(nullptr, Wo, out, 0); // out proj
}

// round 4
// speedup vs baseline: 3.0936x; 1.8871x over previous
#include <cuda_runtime.h>
#include <math.h>
#include <stdint.h>

#define S_LEN  2048
#define DMODEL 1024
#define NHEAD  16
#define DK     64
#define B_SZ   2
#define M_TOT  (B_SZ * S_LEN)      // 4096
#define BH_TOT (B_SZ * NHEAD)      // 32

// ------------------------- scratch (device globals; no allocs allowed) ------
__device__ float g_Q[(size_t)BH_TOT * S_LEN * DK];   // [b,h,s,dk] (pre-scaled 1/8)
__device__ float g_K[(size_t)BH_TOT * S_LEN * DK];
__device__ float g_V[(size_t)BH_TOT * S_LEN * DK];
__device__ float g_O[(size_t)M_TOT * DMODEL];        // [b,s,d]

// ======================= helpers =============================================
__device__ __forceinline__ uint32_t smem_u32(const void* p) {
    uint32_t a;
    asm("{ .reg .u64 t; cvta.to.shared.u64 t, %1; cvt.u32.u64 %0, t; }"
        : "=r"(a) : "l"(p));
    return a;
}
__device__ __forceinline__ uint32_t f32_to_tf32(float f) {
    uint32_t r;
    asm("cvt.rna.tf32.f32 %0, %1;" : "=r"(r) : "f"(f));
    return r;
}
__device__ __forceinline__ void ldsm4(uint32_t r[4], uint32_t addr) {
    asm volatile("ldmatrix.sync.aligned.m8n8.x4.shared.b16 {%0,%1,%2,%3}, [%4];"
                 : "=r"(r[0]), "=r"(r[1]), "=r"(r[2]), "=r"(r[3]) : "r"(addr));
}
__device__ __forceinline__ void mma_tf32(float d[4], const uint32_t a[4],
                                         const uint32_t b[2]) {
    asm volatile("mma.sync.aligned.m16n8k8.row.col.f32.tf32.tf32.f32 "
                 "{%0,%1,%2,%3}, {%4,%5,%6,%7}, {%8,%9}, {%0,%1,%2,%3};"
                 : "+f"(d[0]), "+f"(d[1]), "+f"(d[2]), "+f"(d[3])
                 : "r"(a[0]), "r"(a[1]), "r"(a[2]), "r"(a[3]),
                   "r"(b[0]), "r"(b[1]));
}

// ======================= tf32 GEMM via mma.sync ==============================
#define PA 36
#define GSMEM (2 * 128 * PA * 4)

__global__ __launch_bounds__(256) void gemm_tf32_kernel(
    const float* __restrict__ A, const float* __restrict__ W,
    float* __restrict__ out, int mode)
{
    extern __shared__ float sm[];
    float* As = sm;
    float* Bs = sm + 128 * PA;
    const uint32_t sA = smem_u32(As);

    const float* Ap = (mode == 0) ? g_O : A;
    const int tid = threadIdx.x;
    const int wid = tid >> 5, lane = tid & 31;
    const int wm = (wid >> 2) * 64;
    const int wn = (wid & 3) * 32;
    const int bm = blockIdx.y * 128;
    const int bn = blockIdx.x * 128;

    const int q = lane >> 3, rq = lane & 7;
    const int qm = (q & 1) * 8, qk = (q & 2) * 2;

    float acc[4][4][4];
    #pragma unroll
    for (int mt = 0; mt < 4; mt++)
        #pragma unroll
        for (int nt = 0; nt < 4; nt++)
            #pragma unroll
            for (int i = 0; i < 4; i++) acc[mt][nt][i] = 0.f;

    float4 av[4], bv[4];
    #pragma unroll
    for (int i = 0; i < 4; i++) {
        int f = tid + i * 256, r = f >> 3, c = f & 7;
        av[i] = *(const float4*)(Ap + (size_t)(bm + r) * DMODEL + c * 4);
        bv[i] = *(const float4*)(W  + (size_t)(bn + r) * DMODEL + c * 4);
    }

    for (int t = 0; t < 32; t++) {
        #pragma unroll
        for (int i = 0; i < 4; i++) {
            int f = tid + i * 256, r = f >> 3, c = f & 7;
            uint32_t off = (uint32_t)(r * PA + c * 4) * 4;
            asm volatile("st.shared.v4.b32 [%0], {%1, %2, %3, %4};"
                :: "r"(sA + off),
                   "r"(f32_to_tf32(av[i].x)), "r"(f32_to_tf32(av[i].y)),
                   "r"(f32_to_tf32(av[i].z)), "r"(f32_to_tf32(av[i].w)) : "memory");
            asm volatile("st.shared.v4.b32 [%0], {%1, %2, %3, %4};"
                :: "r"(sA + (uint32_t)(128 * PA * 4) + off),
                   "r"(f32_to_tf32(bv[i].x)), "r"(f32_to_tf32(bv[i].y)),
                   "r"(f32_to_tf32(bv[i].z)), "r"(f32_to_tf32(bv[i].w)) : "memory");
        }
        __syncthreads();
        if (t < 31) {
            int k0 = (t + 1) * 32;
            #pragma unroll
            for (int i = 0; i < 4; i++) {
                int f = tid + i * 256, r = f >> 3, c = f & 7;
                av[i] = *(const float4*)(Ap + (size_t)(bm + r) * DMODEL + k0 + c * 4);
                bv[i] = *(const float4*)(W  + (size_t)(bn + r) * DMODEL + k0 + c * 4);
            }
        }
        #pragma unroll
        for (int ks = 0; ks < 4; ks++) {
            uint32_t aR[4][4], bR[4][2];
            #pragma unroll
            for (int mt = 0; mt < 4; mt++) {
                uint32_t off = (uint32_t)((wm + mt * 16 + qm + rq) * PA +
                                          ks * 8 + qk) * 4;
                ldsm4(aR[mt], sA + off);
            }
            #pragma unroll
            for (int nt = 0; nt < 4; nt++) {
                const float* bp = Bs + (wn + nt * 8 + (lane >> 2)) * PA +
                                  ks * 8 + (lane & 3);
                bR[nt][0] = __float_as_uint(bp[0]);
                bR[nt][1] = __float_as_uint(bp[4]);
            }
            #pragma unroll
            for (int mt = 0; mt < 4; mt++)
                #pragma unroll
                for (int nt = 0; nt < 4; nt++)
                    mma_tf32(acc[mt][nt], aR[mt], bR[nt]);
        }
        __syncthreads();
    }

    const float kf = 0.28782313662425573f;   // ln(10000)/32
    const float qs = (mode == 2) ? 0.125f : 1.0f;   // fold 1/sqrt(dk) into Q
    #pragma unroll
    for (int mt = 0; mt < 4; mt++) {
        #pragma unroll
        for (int nt = 0; nt < 4; nt++) {
            float* a = acc[mt][nt];
            const int col = bn + wn + nt * 8 + 2 * (lane & 3);
            const int rbase = bm + wm + mt * 16 + (lane >> 2);
            if (mode == 0) {
                *(float2*)(out + (size_t)rbase * DMODEL + col) =
                    make_float2(a[0], a[1]);
                *(float2*)(out + (size_t)(rbase + 8) * DMODEL + col) =
                    make_float2(a[2], a[3]);
            } else {
                const int h = col >> 6, d = col & 63;
                float* dst = (mode == 1) ? g_V : (mode == 2 ? g_Q : g_K);
                float fr = 0.f;
                if (mode != 1) fr = expf(-(float)(d >> 1) * kf);
                #pragma unroll
                for (int rr = 0; rr < 2; rr++) {
                    int m = rbase + rr * 8;
                    int b = m >> 11, s = m & 2047;
                    float e = a[rr * 2], o = a[rr * 2 + 1];
                    float2 v;
                    if (mode == 1) {
                        v = make_float2(e, o);
                    } else {
                        float sn, cs;
                        sincosf((float)s * fr, &sn, &cs);
                        v = make_float2((e * cs - o * sn) * qs,
                                        (e * sn + o * cs) * qs);
                    }
                    *(float2*)(dst + ((size_t)(b * NHEAD + h) * S_LEN + s) * DK + d) = v;
                }
            }
        }
    }
}

// ================= causal flash attention via mma.sync tf32 ==================
// CTA: 128 q-rows x (2qt+2) kv-tiles of 64. 8 warps x 16 q-rows.
#define KP 68
#define PP 68
#define FLASH_SMEM ((2 * 64 * KP + 128 * PP) * 4)   // 69632 B

__global__ void __launch_bounds__(256, 2) flash_kernel()
{
    extern __shared__ float smf[];
    float* Ks = smf;                    // [64 kv][KP] k-major
    float* Vs = smf + 64 * KP;          // [64 d][KP] = V^T
    float* Ps = smf + 2 * 64 * KP;      // [128 q][PP]; also Q staging
    const uint32_t sP = smem_u32(Ps);

    const int qt = 15 - blockIdx.x;     // big tiles first
    const int bh = blockIdx.y;
    const float* Qp = g_Q + (size_t)bh * S_LEN * DK;
    const float* Kp = g_K + (size_t)bh * S_LEN * DK;
    const float* Vp = g_V + (size_t)bh * S_LEN * DK;

    const int tid = threadIdx.x;
    const int wid = tid >> 5, lane = tid & 31;
    const int q = lane >> 3, rq = lane & 7;
    const int qm = (q & 1) * 8, qk = (q & 2) * 2;
    const int lq = lane >> 2, lc = lane & 3;

    // ---- stage Q tile into Ps (tf32), then ldmatrix fragments ----
    #pragma unroll
    for (int i = 0; i < 8; i++) {
        int f = tid + i * 256;
        int r = f >> 4, c = f & 15;
        float4 v = *(const float4*)(Qp + (size_t)(qt * 128 + r) * DK + c * 4);
        asm volatile("st.shared.v4.b32 [%0], {%1, %2, %3, %4};"
            :: "r"(sP + (uint32_t)(r * PP + c * 4) * 4),
               "r"(f32_to_tf32(v.x)), "r"(f32_to_tf32(v.y)),
               "r"(f32_to_tf32(v.z)), "r"(f32_to_tf32(v.w)) : "memory");
    }
    __syncthreads();
    uint32_t qf[8][4];
    {
        uint32_t base = sP + (uint32_t)((wid * 16 + qm + rq) * PP + qk) * 4;
        #pragma unroll
        for (int ks = 0; ks < 8; ks++) ldsm4(qf[ks], base + ks * 32);
    }

    float m1 = -INFINITY, m2 = -INFINITY, l1 = 0.f, l2 = 0.f;
    float o[8][4];
    #pragma unroll
    for (int nt = 0; nt < 8; nt++)
        #pragma unroll
        for (int j = 0; j < 4; j++) o[nt][j] = 0.f;

    const int nkt = 2 * qt + 2;
    for (int kt = 0; kt < nkt; kt++) {
        __syncthreads();   // prior readers of Ks/Vs done (iter0: Q ldmatrix done)
        // K tile: row-major, conflict-free v4 stores
        #pragma unroll
        for (int i = 0; i < 4; i++) {
            int f = tid + i * 256;
            int r = f >> 4, c = f & 15;
            float4 v = *(const float4*)(Kp + (size_t)(kt * 64 + r) * DK + c * 4);
            asm volatile("st.shared.v4.b32 [%0], {%1, %2, %3, %4};"
                :: "r"(smem_u32(Ks) + (uint32_t)(r * KP + c * 4) * 4),
                   "r"(f32_to_tf32(v.x)), "r"(f32_to_tf32(v.y)),
                   "r"(f32_to_tf32(v.z)), "r"(f32_to_tf32(v.w)) : "memory");
        }
        // V tile: transposed store; lanes map along kv -> conflict-free
        #pragma unroll
        for (int i = 0; i < 4; i++) {
            int f = tid + i * 256;
            int r = f & 63, c = f >> 6;       // r = kv row, c = d-group
            float4 v = *(const float4*)(Vp + (size_t)(kt * 64 + r) * DK + c * 4);
            float* vd = Vs + (c * 4) * KP + r;
            vd[0 * KP] = __uint_as_float(f32_to_tf32(v.x));
            vd[1 * KP] = __uint_as_float(f32_to_tf32(v.y));
            vd[2 * KP] = __uint_as_float(f32_to_tf32(v.z));
            vd[3 * KP] = __uint_as_float(f32_to_tf32(v.w));
        }
        __syncthreads();

        // ---- S = Q K^T ----
        float s[8][4];
        #pragma unroll
        for (int nt = 0; nt < 8; nt++)
            #pragma unroll
            for (int j = 0; j < 4; j++) s[nt][j] = 0.f;
        #pragma unroll
        for (int ks = 0; ks < 8; ks++) {
            #pragma unroll
            for (int nt = 0; nt < 8; nt++) {
                uint32_t b[2];
                const float* bp = Ks + (nt * 8 + lq) * KP + ks * 8 + lc;
                b[0] = __float_as_uint(bp[0]);
                b[1] = __float_as_uint(bp[4]);
                mma_tf32(s[nt], qf[ks], b);
            }
        }

        // ---- causal mask (only tiles that touch the diagonal) ----
        if (kt >= 2 * qt) {
            const int row1 = qt * 128 + wid * 16 + lq;
            #pragma unroll
            for (int nt = 0; nt < 8; nt++) {
                int colb = kt * 64 + nt * 8 + 2 * lc;
                if (colb     > row1)     s[nt][0] = -INFINITY;
                if (colb + 1 > row1)     s[nt][1] = -INFINITY;
                if (colb     > row1 + 8) s[nt][2] = -INFINITY;
                if (colb + 1 > row1 + 8) s[nt][3] = -INFINITY;
            }
        }

        // ---- online softmax (rows owned by lane quads) ----
        float mx1 = -INFINITY, mx2 = -INFINITY;
        #pragma unroll
        for (int nt = 0; nt < 8; nt++) {
            mx1 = fmaxf(mx1, fmaxf(s[nt][0], s[nt][1]));
            mx2 = fmaxf(mx2, fmaxf(s[nt][2], s[nt][3]));
        }
        mx1 = fmaxf(mx1, __shfl_xor_sync(0xffffffffu, mx1, 1));
        mx1 = fmaxf(mx1, __shfl_xor_sync(0xffffffffu, mx1, 2));
        mx2 = fmaxf(mx2, __shfl_xor_sync(0xffffffffu, mx2, 1));
        mx2 = fmaxf(mx2, __shfl_xor_sync(0xffffffffu, mx2, 2));
        const float nm1 = fmaxf(m1, mx1), nm2 = fmaxf(m2, mx2);
        const float sc1 = __expf(m1 - nm1), sc2 = __expf(m2 - nm2);
        float su1 = 0.f, su2 = 0.f;
        #pragma unroll
        for (int nt = 0; nt < 8; nt++) {
            s[nt][0] = __expf(s[nt][0] - nm1); su1 += s[nt][0];
            s[nt][1] = __expf(s[nt][1] - nm1); su1 += s[nt][1];
            s[nt][2] = __expf(s[nt][2] - nm2); su2 += s[nt][2];
            s[nt][3] = __expf(s[nt][3] - nm2); su2 += s[nt][3];
        }
        su1 += __shfl_xor_sync(0xffffffffu, su1, 1);
        su1 += __shfl_xor_sync(0xffffffffu, su1, 2);
        su2 += __shfl_xor_sync(0xffffffffu, su2, 1);
        su2 += __shfl_xor_sync(0xffffffffu, su2, 2);
        l1 = l1 * sc1 + su1;  m1 = nm1;
        l2 = l2 * sc2 + su2;  m2 = nm2;
        #pragma unroll
        for (int nt = 0; nt < 8; nt++) {
            o[nt][0] *= sc1; o[nt][1] *= sc1;
            o[nt][2] *= sc2; o[nt][3] *= sc2;
        }

        // ---- stage P (warp-private rows) and re-load as A-fragments ----
        {
            uint32_t p1 = sP + (uint32_t)((wid * 16 + lq) * PP + 2 * lc) * 4;
            uint32_t p2 = p1 + (uint32_t)(8 * PP) * 4;
            #pragma unroll
            for (int nt = 0; nt < 8; nt++) {
                asm volatile("st.shared.v2.b32 [%0], {%1, %2};"
                    :: "r"(p1 + nt * 32),
                       "r"(f32_to_tf32(s[nt][0])), "r"(f32_to_tf32(s[nt][1])) : "memory");
                asm volatile("st.shared.v2.b32 [%0], {%1, %2};"
                    :: "r"(p2 + nt * 32),
                       "r"(f32_to_tf32(s[nt][2])), "r"(f32_to_tf32(s[nt][3])) : "memory");
            }
        }
        __syncwarp();

        // ---- O += P V ----
        {
            uint32_t pbase = sP + (uint32_t)((wid * 16 + qm + rq) * PP + qk) * 4;
            #pragma unroll
            for (int ks = 0; ks < 8; ks++) {
                uint32_t pf[4];
                ldsm4(pf, pbase + ks * 32);
                #pragma unroll
                for (int nt = 0; nt < 8; nt++) {
                    uint32_t b[2];
                    const float* bp = Vs + (nt * 8 + lq) * KP + ks * 8 + lc;
                    b[0] = __float_as_uint(bp[0]);
                    b[1] = __float_as_uint(bp[4]);
                    mma_tf32(o[nt], pf, b);
                }
            }
        }
    }

    // ---- normalize and write O in [b,s,d] ----
    const float i1 = 1.f / l1, i2 = 1.f / l2;
    const int b = bh >> 4, h = bh & 15;
    const int row1 = qt * 128 + wid * 16 + lq;
    const size_t base1 = ((size_t)(b * S_LEN + row1)) * DMODEL + h * 64 + 2 * lc;
    const size_t base2 = base1 + (size_t)8 * DMODEL;
    #pragma unroll
    for (int nt = 0; nt < 8; nt++) {
        *(float2*)(g_O + base1 + nt * 8) = make_float2(o[nt][0] * i1, o[nt][1] * i1);
        *(float2*)(g_O + base2 + nt * 8) = make_float2(o[nt][2] * i2, o[nt][3] * i2);
    }
}

// ------------------------- launch -------------------------------------------
extern "C" void kernel_launch(void* const* d_in, const int* in_sizes, int n_in,
                              void* d_out, int out_size)
{
    const float* x  = (const float*)d_in[0];
    const float* Wq = (const float*)d_in[1];
    const float* Wk = (const float*)d_in[2];
    const float* Wv = (const float*)d_in[3];
    const float* Wo = (const float*)d_in[4];
    float* out = (float*)d_out;

    cudaFuncSetAttribute(flash_kernel,
                         cudaFuncAttributeMaxDynamicSharedMemorySize, FLASH_SMEM);

    dim3 ggrid(DMODEL / 128, M_TOT / 128);   // (8, 32)
    gemm_tf32_kernel<<<ggrid, 256, GSMEM>>>(x, Wq, nullptr, 2);   // Q + RoPE (x1/8)
    gemm_tf32_kernel<<<ggrid, 256, GSMEM>>>(x, Wk, nullptr, 3);   // K + RoPE
    gemm_tf32_kernel<<<ggrid, 256, GSMEM>>>(x, Wv, nullptr, 1);   // V

    dim3 fgrid(16, BH_TOT);                  // (16, 32)
    flash_kernel<<<fgrid, 256, FLASH_SMEM>>>();

    gemm_tf32_kernel<<<ggrid, 256, GSMEM>>>(nullptr, Wo, out, 0); // out proj
}

// round 5
// speedup vs baseline: 3.4362x; 1.1108x over previous
#include <cuda_runtime.h>
#include <math.h>
#include <stdint.h>

#define S_LEN  2048
#define DMODEL 1024
#define NHEAD  16
#define DK     64
#define B_SZ   2
#define M_TOT  (B_SZ * S_LEN)      // 4096
#define BH_TOT (B_SZ * NHEAD)      // 32

// ------------------------- scratch (device globals; no allocs allowed) ------
// Q,K: [b,h,s,dk], tf32-rounded, Q pre-scaled by 1/8.  V: [b,h,d,s] (transposed,
// tf32-rounded).  O: [b,s,d] fp32.
__device__ float g_Q[(size_t)BH_TOT * S_LEN * DK];
__device__ float g_K[(size_t)BH_TOT * S_LEN * DK];
__device__ float g_V[(size_t)BH_TOT * S_LEN * DK];
__device__ float g_O[(size_t)M_TOT * DMODEL];

// ======================= helpers =============================================
__device__ __forceinline__ uint32_t smem_u32(const void* p) {
    uint32_t a;
    asm("{ .reg .u64 t; cvta.to.shared.u64 t, %1; cvt.u32.u64 %0, t; }"
        : "=r"(a) : "l"(p));
    return a;
}
__device__ __forceinline__ uint32_t f32_to_tf32(float f) {
    uint32_t r;
    asm("cvt.rna.tf32.f32 %0, %1;" : "=r"(r) : "f"(f));
    return r;
}
__device__ __forceinline__ float tf32r(float f) {
    return __uint_as_float(f32_to_tf32(f));
}
__device__ __forceinline__ void ldsm4(uint32_t r[4], uint32_t addr) {
    asm volatile("ldmatrix.sync.aligned.m8n8.x4.shared.b16 {%0,%1,%2,%3}, [%4];"
                 : "=r"(r[0]), "=r"(r[1]), "=r"(r[2]), "=r"(r[3]) : "r"(addr));
}
__device__ __forceinline__ void mma_tf32(float d[4], const uint32_t a[4],
                                         const uint32_t b[2]) {
    asm volatile("mma.sync.aligned.m16n8k8.row.col.f32.tf32.tf32.f32 "
                 "{%0,%1,%2,%3}, {%4,%5,%6,%7}, {%8,%9}, {%0,%1,%2,%3};"
                 : "+f"(d[0]), "+f"(d[1]), "+f"(d[2]), "+f"(d[3])
                 : "r"(a[0]), "r"(a[1]), "r"(a[2]), "r"(a[3]),
                   "r"(b[0]), "r"(b[1]));
}
#define CP_ASYNC16(dst, src) \
    asm volatile("cp.async.cg.shared.global [%0], [%1], 16;" \
                 :: "r"(dst), "l"(src) : "memory")
#define CP_COMMIT() asm volatile("cp.async.commit_group;" ::: "memory")
#define CP_WAIT0()  asm volatile("cp.async.wait_group 0;" ::: "memory")

// ======================= tf32 GEMM via mma.sync ==============================
#define PA 36
#define GSMEM (2 * 128 * PA * 4)

__global__ __launch_bounds__(256) void gemm_tf32_kernel(
    const float* __restrict__ A, const float* __restrict__ W,
    float* __restrict__ out, int mode)
{
    extern __shared__ float sm[];
    float* As = sm;
    float* Bs = sm + 128 * PA;
    const uint32_t sA = smem_u32(As);

    const float* Ap = (mode == 0) ? g_O : A;
    const int tid = threadIdx.x;
    const int wid = tid >> 5, lane = tid & 31;
    const int wm = (wid >> 2) * 64;
    const int wn = (wid & 3) * 32;
    const int bm = blockIdx.y * 128;
    const int bn = blockIdx.x * 128;

    const int q = lane >> 3, rq = lane & 7;
    const int qm = (q & 1) * 8, qk = (q & 2) * 2;

    float acc[4][4][4];
    #pragma unroll
    for (int mt = 0; mt < 4; mt++)
        #pragma unroll
        for (int nt = 0; nt < 4; nt++)
            #pragma unroll
            for (int i = 0; i < 4; i++) acc[mt][nt][i] = 0.f;

    float4 av[4], bv[4];
    #pragma unroll
    for (int i = 0; i < 4; i++) {
        int f = tid + i * 256, r = f >> 3, c = f & 7;
        av[i] = *(const float4*)(Ap + (size_t)(bm + r) * DMODEL + c * 4);
        bv[i] = *(const float4*)(W  + (size_t)(bn + r) * DMODEL + c * 4);
    }

    for (int t = 0; t < 32; t++) {
        #pragma unroll
        for (int i = 0; i < 4; i++) {
            int f = tid + i * 256, r = f >> 3, c = f & 7;
            uint32_t off = (uint32_t)(r * PA + c * 4) * 4;
            asm volatile("st.shared.v4.b32 [%0], {%1, %2, %3, %4};"
                :: "r"(sA + off),
                   "r"(f32_to_tf32(av[i].x)), "r"(f32_to_tf32(av[i].y)),
                   "r"(f32_to_tf32(av[i].z)), "r"(f32_to_tf32(av[i].w)) : "memory");
            asm volatile("st.shared.v4.b32 [%0], {%1, %2, %3, %4};"
                :: "r"(sA + (uint32_t)(128 * PA * 4) + off),
                   "r"(f32_to_tf32(bv[i].x)), "r"(f32_to_tf32(bv[i].y)),
                   "r"(f32_to_tf32(bv[i].z)), "r"(f32_to_tf32(bv[i].w)) : "memory");
        }
        __syncthreads();
        if (t < 31) {
            int k0 = (t + 1) * 32;
            #pragma unroll
            for (int i = 0; i < 4; i++) {
                int f = tid + i * 256, r = f >> 3, c = f & 7;
                av[i] = *(const float4*)(Ap + (size_t)(bm + r) * DMODEL + k0 + c * 4);
                bv[i] = *(const float4*)(W  + (size_t)(bn + r) * DMODEL + k0 + c * 4);
            }
        }
        #pragma unroll
        for (int ks = 0; ks < 4; ks++) {
            uint32_t aR[4][4], bR[4][2];
            #pragma unroll
            for (int mt = 0; mt < 4; mt++) {
                uint32_t off = (uint32_t)((wm + mt * 16 + qm + rq) * PA +
                                          ks * 8 + qk) * 4;
                ldsm4(aR[mt], sA + off);
            }
            #pragma unroll
            for (int nt = 0; nt < 4; nt++) {
                const float* bp = Bs + (wn + nt * 8 + (lane >> 2)) * PA +
                                  ks * 8 + (lane & 3);
                bR[nt][0] = __float_as_uint(bp[0]);
                bR[nt][1] = __float_as_uint(bp[4]);
            }
            #pragma unroll
            for (int mt = 0; mt < 4; mt++)
                #pragma unroll
                for (int nt = 0; nt < 4; nt++)
                    mma_tf32(acc[mt][nt], aR[mt], bR[nt]);
        }
        __syncthreads();
    }

    const float kf = 0.28782313662425573f;   // ln(10000)/32
    #pragma unroll
    for (int mt = 0; mt < 4; mt++) {
        #pragma unroll
        for (int nt = 0; nt < 4; nt++) {
            float* a = acc[mt][nt];
            const int col = bn + wn + nt * 8 + 2 * (lane & 3);
            const int rbase = bm + wm + mt * 16 + (lane >> 2);
            if (mode == 0) {
                *(float2*)(out + (size_t)rbase * DMODEL + col) =
                    make_float2(a[0], a[1]);
                *(float2*)(out + (size_t)(rbase + 8) * DMODEL + col) =
                    make_float2(a[2], a[3]);
            } else if (mode == 1) {
                // V: write transposed [b,h,d,s], tf32-rounded
                const int h = col >> 6, d = col & 63;
                #pragma unroll
                for (int rr = 0; rr < 2; rr++) {
                    int m = rbase + rr * 8;
                    int b = m >> 11, s = m & 2047;
                    float* base = g_V + ((size_t)(b * NHEAD + h) * DK) * S_LEN;
                    base[(size_t)d * S_LEN + s]       = tf32r(a[rr * 2]);
                    base[(size_t)(d + 1) * S_LEN + s] = tf32r(a[rr * 2 + 1]);
                }
            } else {
                // Q (mode 2, scaled 1/8) / K (mode 3): RoPE + tf32 round
                const int h = col >> 6, d = col & 63;
                const float qs = (mode == 2) ? 0.125f : 1.0f;
                float* dst = (mode == 2) ? g_Q : g_K;
                float fr = expf(-(float)(d >> 1) * kf);
                #pragma unroll
                for (int rr = 0; rr < 2; rr++) {
                    int m = rbase + rr * 8;
                    int b = m >> 11, s = m & 2047;
                    float e = a[rr * 2], o = a[rr * 2 + 1];
                    float sn, cs;
                    sincosf((float)s * fr, &sn, &cs);
                    float2 v = make_float2(tf32r((e * cs - o * sn) * qs),
                                           tf32r((e * sn + o * cs) * qs));
                    *(float2*)(dst + ((size_t)(b * NHEAD + h) * S_LEN + s) * DK + d) = v;
                }
            }
        }
    }
}

// ================= causal flash attention via mma.sync tf32 ==================
// CTA: 128 q-rows x (2qt+2) kv-tiles of 64. 8 warps x 16 q-rows.
// K/V^T tiles double-buffered via cp.async (inputs pre-rounded to tf32).
#define KP 68
#define PP 68
#define KV_TILE_F (64 * KP)                 // floats per K (or V) tile
#define BUF_F     (2 * KV_TILE_F)           // K+V per buffer
#define FLASH_SMEM ((2 * BUF_F + 128 * PP) * 4)   // 104448 B

__global__ void __launch_bounds__(256, 2) flash_kernel()
{
    extern __shared__ float smf[];
    float* Ps = smf + 2 * BUF_F;
    const uint32_t sK = smem_u32(smf);
    const uint32_t sP = smem_u32(Ps);

    const int qt = 15 - blockIdx.x;
    const int bh = blockIdx.y;
    const float* Qp  = g_Q + (size_t)bh * S_LEN * DK;
    const float* Kp  = g_K + (size_t)bh * S_LEN * DK;
    const float* Vtp = g_V + (size_t)bh * S_LEN * DK;   // [d][s]

    const int tid = threadIdx.x;
    const int wid = tid >> 5, lane = tid & 31;
    const int q = lane >> 3, rq = lane & 7;
    const int qm = (q & 1) * 8, qk = (q & 2) * 2;
    const int lq = lane >> 2, lc = lane & 3;

    const int cr = tid >> 4, cc = tid & 15;   // copy thread map: row, 16B-chunk

    // ---- preload kv-tile 0 ----
    {
        uint32_t kb = sK;
        uint32_t vb = sK + KV_TILE_F * 4;
        uint32_t doff = (uint32_t)(cr * KP + cc * 4) * 4;
        #pragma unroll
        for (int i = 0; i < 4; i++) {
            int r = cr + i * 16;
            CP_ASYNC16(kb + doff + i * 16 * KP * 4,
                       Kp + (size_t)r * DK + cc * 4);
            CP_ASYNC16(vb + doff + i * 16 * KP * 4,
                       Vtp + (size_t)r * S_LEN + cc * 4);
        }
        CP_COMMIT();
    }

    // ---- stage Q tile (already tf32) and build fragments ----
    #pragma unroll
    for (int i = 0; i < 8; i++) {
        int f = tid + i * 256;
        int r = f >> 4, c = f & 15;
        float4 v = *(const float4*)(Qp + (size_t)(qt * 128 + r) * DK + c * 4);
        *(float4*)&Ps[r * PP + c * 4] = v;
    }
    __syncthreads();
    uint32_t qf[8][4];
    {
        uint32_t base = sP + (uint32_t)((wid * 16 + qm + rq) * PP + qk) * 4;
        #pragma unroll
        for (int ks = 0; ks < 8; ks++) ldsm4(qf[ks], base + ks * 32);
    }

    float m1 = -INFINITY, m2 = -INFINITY, l1 = 0.f, l2 = 0.f;
    float o[8][4];
    #pragma unroll
    for (int nt = 0; nt < 8; nt++)
        #pragma unroll
        for (int j = 0; j < 4; j++) o[nt][j] = 0.f;

    const int nkt = 2 * qt + 2;
    for (int kt = 0; kt < nkt; kt++) {
        const int buf = kt & 1;
        CP_WAIT0();            // tile kt arrived (this thread's copies)
        __syncthreads();       // all threads' copies visible; prior compute done

        if (kt + 1 < nkt) {    // preload next tile into other buffer
            uint32_t kb = sK + (uint32_t)((buf ^ 1) * BUF_F) * 4;
            uint32_t vb = kb + KV_TILE_F * 4;
            uint32_t doff = (uint32_t)(cr * KP + cc * 4) * 4;
            const float* Kn = Kp + (size_t)(kt + 1) * 64 * DK;
            const float* Vn = Vtp + (size_t)(kt + 1) * 64;
            #pragma unroll
            for (int i = 0; i < 4; i++) {
                int r = cr + i * 16;
                CP_ASYNC16(kb + doff + i * 16 * KP * 4,
                           Kn + (size_t)r * DK + cc * 4);
                CP_ASYNC16(vb + doff + i * 16 * KP * 4,
                           Vn + (size_t)r * S_LEN + cc * 4);
            }
            CP_COMMIT();
        }

        const float* Ks = smf + buf * BUF_F;
        const float* Vs = Ks + KV_TILE_F;

        // ---- S = Q K^T ----
        float s[8][4];
        #pragma unroll
        for (int nt = 0; nt < 8; nt++)
            #pragma unroll
            for (int j = 0; j < 4; j++) s[nt][j] = 0.f;
        #pragma unroll
        for (int ks = 0; ks < 8; ks++) {
            #pragma unroll
            for (int nt = 0; nt < 8; nt++) {
                uint32_t b[2];
                const float* bp = Ks + (nt * 8 + lq) * KP + ks * 8 + lc;
                b[0] = __float_as_uint(bp[0]);
                b[1] = __float_as_uint(bp[4]);
                mma_tf32(s[nt], qf[ks], b);
            }
        }

        // ---- causal mask ----
        if (kt >= 2 * qt) {
            const int row1 = qt * 128 + wid * 16 + lq;
            #pragma unroll
            for (int nt = 0; nt < 8; nt++) {
                int colb = kt * 64 + nt * 8 + 2 * lc;
                if (colb     > row1)     s[nt][0] = -INFINITY;
                if (colb + 1 > row1)     s[nt][1] = -INFINITY;
                if (colb     > row1 + 8) s[nt][2] = -INFINITY;
                if (colb + 1 > row1 + 8) s[nt][3] = -INFINITY;
            }
        }

        // ---- online softmax ----
        float mx1 = -INFINITY, mx2 = -INFINITY;
        #pragma unroll
        for (int nt = 0; nt < 8; nt++) {
            mx1 = fmaxf(mx1, fmaxf(s[nt][0], s[nt][1]));
            mx2 = fmaxf(mx2, fmaxf(s[nt][2], s[nt][3]));
        }
        mx1 = fmaxf(mx1, __shfl_xor_sync(0xffffffffu, mx1, 1));
        mx1 = fmaxf(mx1, __shfl_xor_sync(0xffffffffu, mx1, 2));
        mx2 = fmaxf(mx2, __shfl_xor_sync(0xffffffffu, mx2, 1));
        mx2 = fmaxf(mx2, __shfl_xor_sync(0xffffffffu, mx2, 2));
        const float nm1 = fmaxf(m1, mx1), nm2 = fmaxf(m2, mx2);
        const float sc1 = __expf(m1 - nm1), sc2 = __expf(m2 - nm2);
        float su1 = 0.f, su2 = 0.f;
        #pragma unroll
        for (int nt = 0; nt < 8; nt++) {
            s[nt][0] = __expf(s[nt][0] - nm1); su1 += s[nt][0];
            s[nt][1] = __expf(s[nt][1] - nm1); su1 += s[nt][1];
            s[nt][2] = __expf(s[nt][2] - nm2); su2 += s[nt][2];
            s[nt][3] = __expf(s[nt][3] - nm2); su2 += s[nt][3];
        }
        su1 += __shfl_xor_sync(0xffffffffu, su1, 1);
        su1 += __shfl_xor_sync(0xffffffffu, su1, 2);
        su2 += __shfl_xor_sync(0xffffffffu, su2, 1);
        su2 += __shfl_xor_sync(0xffffffffu, su2, 2);
        l1 = l1 * sc1 + su1;  m1 = nm1;
        l2 = l2 * sc2 + su2;  m2 = nm2;
        #pragma unroll
        for (int nt = 0; nt < 8; nt++) {
            o[nt][0] *= sc1; o[nt][1] *= sc1;
            o[nt][2] *= sc2; o[nt][3] *= sc2;
        }

        // ---- stage P (warp-private rows) ----
        {
            uint32_t p1 = sP + (uint32_t)((wid * 16 + lq) * PP + 2 * lc) * 4;
            uint32_t p2 = p1 + (uint32_t)(8 * PP) * 4;
            #pragma unroll
            for (int nt = 0; nt < 8; nt++) {
                asm volatile("st.shared.v2.b32 [%0], {%1, %2};"
                    :: "r"(p1 + nt * 32),
                       "r"(f32_to_tf32(s[nt][0])), "r"(f32_to_tf32(s[nt][1])) : "memory");
                asm volatile("st.shared.v2.b32 [%0], {%1, %2};"
                    :: "r"(p2 + nt * 32),
                       "r"(f32_to_tf32(s[nt][2])), "r"(f32_to_tf32(s[nt][3])) : "memory");
            }
        }
        __syncwarp();

        // ---- O += P V ----
        {
            uint32_t pbase = sP + (uint32_t)((wid * 16 + qm + rq) * PP + qk) * 4;
            #pragma unroll
            for (int ks = 0; ks < 8; ks++) {
                uint32_t pf[4];
                ldsm4(pf, pbase + ks * 32);
                #pragma unroll
                for (int nt = 0; nt < 8; nt++) {
                    uint32_t b[2];
                    const float* bp = Vs + (nt * 8 + lq) * KP + ks * 8 + lc;
                    b[0] = __float_as_uint(bp[0]);
                    b[1] = __float_as_uint(bp[4]);
                    mma_tf32(o[nt], pf, b);
                }
            }
        }
    }

    // ---- normalize and write O in [b,s,d] ----
    const float i1 = 1.f / l1, i2 = 1.f / l2;
    const int b = bh >> 4, h = bh & 15;
    const int row1 = qt * 128 + wid * 16 + lq;
    const size_t base1 = ((size_t)(b * S_LEN + row1)) * DMODEL + h * 64 + 2 * lc;
    const size_t base2 = base1 + (size_t)8 * DMODEL;
    #pragma unroll
    for (int nt = 0; nt < 8; nt++) {
        *(float2*)(g_O + base1 + nt * 8) = make_float2(o[nt][0] * i1, o[nt][1] * i1);
        *(float2*)(g_O + base2 + nt * 8) = make_float2(o[nt][2] * i2, o[nt][3] * i2);
    }
}

// ------------------------- launch -------------------------------------------
extern "C" void kernel_launch(void* const* d_in, const int* in_sizes, int n_in,
                              void* d_out, int out_size)
{
    const float* x  = (const float*)d_in[0];
    const float* Wq = (const float*)d_in[1];
    const float* Wk = (const float*)d_in[2];
    const float* Wv = (const float*)d_in[3];
    const float* Wo = (const float*)d_in[4];
    float* out = (float*)d_out;

    cudaFuncSetAttribute(flash_kernel,
                         cudaFuncAttributeMaxDynamicSharedMemorySize, FLASH_SMEM);

    dim3 ggrid(DMODEL / 128, M_TOT / 128);   // (8, 32)
    gemm_tf32_kernel<<<ggrid, 256, GSMEM>>>(x, Wq, nullptr, 2);   // Q + RoPE (x1/8)
    gemm_tf32_kernel<<<ggrid, 256, GSMEM>>>(x, Wk, nullptr, 3);   // K + RoPE
    gemm_tf32_kernel<<<ggrid, 256, GSMEM>>>(x, Wv, nullptr, 1);   // V (transposed)

    dim3 fgrid(16, BH_TOT);                  // (16, 32)
    flash_kernel<<<fgrid, 256, FLASH_SMEM>>>();

    gemm_tf32_kernel<<<ggrid, 256, GSMEM>>>(nullptr, Wo, out, 0); // out proj
}

// round 7
// speedup vs baseline: 4.5249x; 1.3168x over previous
#include <cuda_runtime.h>
#include <math.h>
#include <stdint.h>

#define S_LEN  2048
#define DMODEL 1024
#define NHEAD  16
#define DK     64
#define B_SZ   2
#define M_TOT  (B_SZ * S_LEN)      // 4096
#define BH_TOT (B_SZ * NHEAD)      // 32

// ------------------------- scratch (device globals; no allocs allowed) ------
// Q,K: [b,h,s,dk] tf32 (Q pre-scaled 1/8). V: [b,h,d,s] tf32. O: [b,s,d] tf32.
// X: tf32(x). Wr: tf32(Wq|Wk|Wv|Wo) concatenated.
__device__ float g_Q[(size_t)BH_TOT * S_LEN * DK];
__device__ float g_K[(size_t)BH_TOT * S_LEN * DK];
__device__ float g_V[(size_t)BH_TOT * S_LEN * DK];
__device__ float g_O[(size_t)M_TOT * DMODEL];
__device__ float g_X[(size_t)M_TOT * DMODEL];
__device__ float g_Wr[(size_t)4 * DMODEL * DMODEL];

// ======================= helpers =============================================
__device__ __forceinline__ uint32_t smem_u32(const void* p) {
    uint32_t a;
    asm("{ .reg .u64 t; cvta.to.shared.u64 t, %1; cvt.u32.u64 %0, t; }"
        : "=r"(a) : "l"(p));
    return a;
}
__device__ __forceinline__ uint32_t f32_to_tf32(float f) {
    uint32_t r;
    asm("cvt.rna.tf32.f32 %0, %1;" : "=r"(r) : "f"(f));
    return r;
}
__device__ __forceinline__ float tf32r(float f) {
    return __uint_as_float(f32_to_tf32(f));
}
__device__ __forceinline__ void ldsm4(uint32_t r[4], uint32_t addr) {
    asm volatile("ldmatrix.sync.aligned.m8n8.x4.shared.b16 {%0,%1,%2,%3}, [%4];"
                 : "=r"(r[0]), "=r"(r[1]), "=r"(r[2]), "=r"(r[3]) : "r"(addr));
}
__device__ __forceinline__ void mma_tf32(float d[4], const uint32_t a[4],
                                         const uint32_t b[2]) {
    asm volatile("mma.sync.aligned.m16n8k8.row.col.f32.tf32.tf32.f32 "
                 "{%0,%1,%2,%3}, {%4,%5,%6,%7}, {%8,%9}, {%0,%1,%2,%3};"
                 : "+f"(d[0]), "+f"(d[1]), "+f"(d[2]), "+f"(d[3])
                 : "r"(a[0]), "r"(a[1]), "r"(a[2]), "r"(a[3]),
                   "r"(b[0]), "r"(b[1]));
}
#define CP_ASYNC16(dst, src) \
    asm volatile("cp.async.cg.shared.global [%0], [%1], 16;" \
                 :: "r"(dst), "l"(src) : "memory")
#define CP_COMMIT() asm volatile("cp.async.commit_group;" ::: "memory")
#define CP_WAIT0()  asm volatile("cp.async.wait_group 0;" ::: "memory")
#define CP_WAIT1()  asm volatile("cp.async.wait_group 1;" ::: "memory")

// ======================= pre-pass: round x, W to tf32 ========================
__global__ __launch_bounds__(256) void prepass_kernel(
    const float4* __restrict__ x,  const float4* __restrict__ wq,
    const float4* __restrict__ wk, const float4* __restrict__ wv,
    const float4* __restrict__ wo)
{
    int idx = blockIdx.x * 256 + threadIdx.x;   // 0 .. 2097151
    float4 v; float4* dst;
    if (idx < 1048576) {
        v = x[idx]; dst = (float4*)g_X + idx;
    } else {
        int r = idx - 1048576;
        int which = r >> 18, off = r & 262143;
        const float4* src = (which == 0) ? wq : (which == 1) ? wk
                          : (which == 2) ? wv : wo;
        v = src[off];
        dst = (float4*)g_Wr + ((size_t)which << 18) + off;
    }
    v.x = tf32r(v.x); v.y = tf32r(v.y); v.z = tf32r(v.z); v.w = tf32r(v.w);
    *dst = v;
}

// ======================= tf32 GEMM (cp.async double-buffered) ================
// C[m,n] = sum_k A[m,k] * W[n,k]. Tile 128x128, BK=32, 8 warps (2m x 4n).
// job 0: out-proj (A=g_O, W=Wr[3], write out fp32)
// job 1: fused QKV (blockIdx.x selects which projection + n-block)
#define PA 36
#define GTILE (128 * PA)
#define GSMEM (4 * GTILE * 4)   // 2 bufs x (A+B) = 73728 B

__global__ void __launch_bounds__(256, 2) gemm_kernel(float* __restrict__ out,
                                                      int job)
{
    extern __shared__ float smg[];
    const uint32_t sG = smem_u32(smg);

    const int tid = threadIdx.x;
    const int wid = tid >> 5, lane = tid & 31;
    const int wm = (wid >> 2) * 64;
    const int wn = (wid & 3) * 32;
    const int bm = blockIdx.y * 128;

    int bn, mode;
    const float *Ap, *Wp;
    if (job == 0) {
        Ap = g_O; Wp = g_Wr + 3 * 1048576; mode = 0; bn = blockIdx.x * 128;
    } else {
        int which = blockIdx.x >> 3;
        bn = (blockIdx.x & 7) * 128;
        Ap = g_X; Wp = g_Wr + (size_t)which * 1048576;
        mode = (which == 2) ? 1 : which + 2;   // 0->Q(2), 1->K(3), 2->V(1)
    }

    const int q = lane >> 3, rq = lane & 7;
    const int qm = (q & 1) * 8, qk = (q & 2) * 2;
    const int brow = (lane & 7) + ((lane >> 4) << 3);
    const int bcol = ((lane >> 3) & 1) * 4;

    float acc[4][4][4];
    #pragma unroll
    for (int mt = 0; mt < 4; mt++)
        #pragma unroll
        for (int nt = 0; nt < 4; nt++)
            #pragma unroll
            for (int i = 0; i < 4; i++) acc[mt][nt][i] = 0.f;

    const int cr = tid >> 3, cch = tid & 7;   // copy map: row, 16B chunk
    // preload tile 0 -> buf 0
    {
        uint32_t ab = sG, bb = sG + GTILE * 4;
        uint32_t doff = (uint32_t)(cr * PA + cch * 4) * 4;
        #pragma unroll
        for (int i = 0; i < 4; i++) {
            int r = cr + i * 32;
            CP_ASYNC16(ab + doff + (uint32_t)(i * 32 * PA) * 4,
                       Ap + (size_t)(bm + r) * DMODEL + cch * 4);
            CP_ASYNC16(bb + doff + (uint32_t)(i * 32 * PA) * 4,
                       Wp + (size_t)(bn + r) * DMODEL + cch * 4);
        }
        CP_COMMIT();
    }

    for (int t = 0; t < 32; t++) {
        const int buf = t & 1;
        if (t < 31) {
            int k0 = (t + 1) * 32;
            uint32_t ab = sG + (uint32_t)((buf ^ 1) * 2 * GTILE) * 4;
            uint32_t bb = ab + GTILE * 4;
            uint32_t doff = (uint32_t)(cr * PA + cch * 4) * 4;
            #pragma unroll
            for (int i = 0; i < 4; i++) {
                int r = cr + i * 32;
                CP_ASYNC16(ab + doff + (uint32_t)(i * 32 * PA) * 4,
                           Ap + (size_t)(bm + r) * DMODEL + k0 + cch * 4);
                CP_ASYNC16(bb + doff + (uint32_t)(i * 32 * PA) * 4,
                           Wp + (size_t)(bn + r) * DMODEL + k0 + cch * 4);
            }
            CP_COMMIT();
            CP_WAIT1();
        } else {
            CP_WAIT0();
        }
        __syncthreads();

        const uint32_t aB = sG + (uint32_t)(buf * 2 * GTILE) * 4;
        const uint32_t bB = aB + (uint32_t)GTILE * 4;
        #pragma unroll
        for (int ks = 0; ks < 4; ks++) {
            uint32_t aR[4][4], b0[4], b1[4];
            #pragma unroll
            for (int mt = 0; mt < 4; mt++)
                ldsm4(aR[mt], aB + (uint32_t)((wm + mt * 16 + qm + rq) * PA +
                                              ks * 8 + qk) * 4);
            ldsm4(b0, bB + (uint32_t)((wn + brow) * PA + ks * 8 + bcol) * 4);
            ldsm4(b1, bB + (uint32_t)((wn + 16 + brow) * PA + ks * 8 + bcol) * 4);
            #pragma unroll
            for (int mt = 0; mt < 4; mt++) {
                mma_tf32(acc[mt][0], aR[mt], &b0[0]);
                mma_tf32(acc[mt][1], aR[mt], &b0[2]);
                mma_tf32(acc[mt][2], aR[mt], &b1[0]);
                mma_tf32(acc[mt][3], aR[mt], &b1[2]);
            }
        }
        __syncthreads();
    }

    // ---------------- epilogue ------------------------------------------------
    const float kf = 0.28782313662425573f;   // ln(10000)/32
    #pragma unroll
    for (int mt = 0; mt < 4; mt++) {
        #pragma unroll
        for (int nt = 0; nt < 4; nt++) {
            float* a = acc[mt][nt];
            const int col = bn + wn + nt * 8 + 2 * (lane & 3);
            const int rbase = bm + wm + mt * 16 + (lane >> 2);
            if (mode == 0) {
                *(float2*)(out + (size_t)rbase * DMODEL + col) =
                    make_float2(a[0], a[1]);
                *(float2*)(out + (size_t)(rbase + 8) * DMODEL + col) =
                    make_float2(a[2], a[3]);
            } else if (mode == 1) {
                const int h = col >> 6, d = col & 63;
                #pragma unroll
                for (int rr = 0; rr < 2; rr++) {
                    int m = rbase + rr * 8;
                    int b = m >> 11, s = m & 2047;
                    float* base = g_V + ((size_t)(b * NHEAD + h) * DK) * S_LEN;
                    base[(size_t)d * S_LEN + s]       = tf32r(a[rr * 2]);
                    base[(size_t)(d + 1) * S_LEN + s] = tf32r(a[rr * 2 + 1]);
                }
            } else {
                const int h = col >> 6, d = col & 63;
                const float qs = (mode == 2) ? 0.125f : 1.0f;
                float* dst = (mode == 2) ? g_Q : g_K;
                float fr = expf(-(float)(d >> 1) * kf);
                #pragma unroll
                for (int rr = 0; rr < 2; rr++) {
                    int m = rbase + rr * 8;
                    int b = m >> 11, s = m & 2047;
                    float e = a[rr * 2], o = a[rr * 2 + 1];
                    float sn, cs;
                    sincosf((float)s * fr, &sn, &cs);
                    float2 v = make_float2(tf32r((e * cs - o * sn) * qs),
                                           tf32r((e * sn + o * cs) * qs));
                    *(float2*)(dst + ((size_t)(b * NHEAD + h) * S_LEN + s) * DK + d) = v;
                }
            }
        }
    }
}

// ================= causal flash attention via mma.sync tf32 ==================
#define KP 68
#define PP 68
#define KV_TILE_F (64 * KP)
#define BUF_F     (2 * KV_TILE_F)
#define FLASH_SMEM ((2 * BUF_F + 128 * PP) * 4)   // 104448 B

__global__ void __launch_bounds__(256, 2) flash_kernel()
{
    extern __shared__ float smf[];
    float* Ps = smf + 2 * BUF_F;
    const uint32_t sK = smem_u32(smf);
    const uint32_t sP = smem_u32(Ps);

    const int qt = 15 - blockIdx.y;     // big tiles first (bh fastest)
    const int bh = blockIdx.x;
    const float* Qp  = g_Q + (size_t)bh * S_LEN * DK;
    const float* Kp  = g_K + (size_t)bh * S_LEN * DK;
    const float* Vtp = g_V + (size_t)bh * S_LEN * DK;   // [d][s]

    const int tid = threadIdx.x;
    const int wid = tid >> 5, lane = tid & 31;
    const int q = lane >> 3, rq = lane & 7;
    const int qm = (q & 1) * 8, qk = (q & 2) * 2;
    const int lq = lane >> 2, lc = lane & 3;
    const int brow = (lane & 7) + ((lane >> 4) << 3);
    const int bcol = ((lane >> 3) & 1) * 4;

    const int cr = tid >> 4, cc = tid & 15;

    // ---- preload kv-tile 0 ----
    {
        uint32_t kb = sK, vb = sK + KV_TILE_F * 4;
        uint32_t doff = (uint32_t)(cr * KP + cc * 4) * 4;
        #pragma unroll
        for (int i = 0; i < 4; i++) {
            int r = cr + i * 16;
            CP_ASYNC16(kb + doff + (uint32_t)(i * 16 * KP) * 4,
                       Kp + (size_t)r * DK + cc * 4);
            CP_ASYNC16(vb + doff + (uint32_t)(i * 16 * KP) * 4,
                       Vtp + (size_t)r * S_LEN + cc * 4);
        }
        CP_COMMIT();
    }

    // ---- stage Q tile (tf32 already) and build fragments ----
    #pragma unroll
    for (int i = 0; i < 8; i++) {
        int f = tid + i * 256;
        int r = f >> 4, c = f & 15;
        float4 v = *(const float4*)(Qp + (size_t)(qt * 128 + r) * DK + c * 4);
        *(float4*)&Ps[r * PP + c * 4] = v;
    }
    __syncthreads();
    uint32_t qf[8][4];
    {
        uint32_t base = sP + (uint32_t)((wid * 16 + qm + rq) * PP + qk) * 4;
        #pragma unroll
        for (int ks = 0; ks < 8; ks++) ldsm4(qf[ks], base + ks * 32);
    }

    float m1 = -INFINITY, m2 = -INFINITY, l1 = 0.f, l2 = 0.f;
    float o[8][4];
    #pragma unroll
    for (int nt = 0; nt < 8; nt++)
        #pragma unroll
        for (int j = 0; j < 4; j++) o[nt][j] = 0.f;

    const int nkt = 2 * qt + 2;
    for (int kt = 0; kt < nkt; kt++) {
        const int buf = kt & 1;
        CP_WAIT0();
        __syncthreads();

        if (kt + 1 < nkt) {
            uint32_t kb = sK + (uint32_t)((buf ^ 1) * BUF_F) * 4;
            uint32_t vb = kb + (uint32_t)KV_TILE_F * 4;
            uint32_t doff = (uint32_t)(cr * KP + cc * 4) * 4;
            const float* Kn = Kp + (size_t)(kt + 1) * 64 * DK;
            const float* Vn = Vtp + (size_t)(kt + 1) * 64;
            #pragma unroll
            for (int i = 0; i < 4; i++) {
                int r = cr + i * 16;
                CP_ASYNC16(kb + doff + (uint32_t)(i * 16 * KP) * 4,
                           Kn + (size_t)r * DK + cc * 4);
                CP_ASYNC16(vb + doff + (uint32_t)(i * 16 * KP) * 4,
                           Vn + (size_t)r * S_LEN + cc * 4);
            }
            CP_COMMIT();
        }

        const uint32_t sKb = sK + (uint32_t)(buf * BUF_F) * 4;
        const uint32_t sVb = sKb + (uint32_t)KV_TILE_F * 4;

        // ---- S = Q K^T ----
        float s[8][4];
        #pragma unroll
        for (int nt = 0; nt < 8; nt++)
            #pragma unroll
            for (int j = 0; j < 4; j++) s[nt][j] = 0.f;
        #pragma unroll
        for (int ks = 0; ks < 8; ks++) {
            #pragma unroll
            for (int nt2 = 0; nt2 < 4; nt2++) {
                uint32_t bb[4];
                ldsm4(bb, sKb + (uint32_t)((nt2 * 16 + brow) * KP +
                                           ks * 8 + bcol) * 4);
                mma_tf32(s[2 * nt2],     qf[ks], &bb[0]);
                mma_tf32(s[2 * nt2 + 1], qf[ks], &bb[2]);
            }
        }

        // ---- causal mask ----
        if (kt >= 2 * qt) {
            const int row1 = qt * 128 + wid * 16 + lq;
            #pragma unroll
            for (int nt = 0; nt < 8; nt++) {
                int colb = kt * 64 + nt * 8 + 2 * lc;
                if (colb     > row1)     s[nt][0] = -INFINITY;
                if (colb + 1 > row1)     s[nt][1] = -INFINITY;
                if (colb     > row1 + 8) s[nt][2] = -INFINITY;
                if (colb + 1 > row1 + 8) s[nt][3] = -INFINITY;
            }
        }

        // ---- online softmax ----
        float mx1 = -INFINITY, mx2 = -INFINITY;
        #pragma unroll
        for (int nt = 0; nt < 8; nt++) {
            mx1 = fmaxf(mx1, fmaxf(s[nt][0], s[nt][1]));
            mx2 = fmaxf(mx2, fmaxf(s[nt][2], s[nt][3]));
        }
        mx1 = fmaxf(mx1, __shfl_xor_sync(0xffffffffu, mx1, 1));
        mx1 = fmaxf(mx1, __shfl_xor_sync(0xffffffffu, mx1, 2));
        mx2 = fmaxf(mx2, __shfl_xor_sync(0xffffffffu, mx2, 1));
        mx2 = fmaxf(mx2, __shfl_xor_sync(0xffffffffu, mx2, 2));
        const float nm1 = fmaxf(m1, mx1), nm2 = fmaxf(m2, mx2);
        const float sc1 = __expf(m1 - nm1), sc2 = __expf(m2 - nm2);
        float su1 = 0.f, su2 = 0.f;
        #pragma unroll
        for (int nt = 0; nt < 8; nt++) {
            s[nt][0] = __expf(s[nt][0] - nm1); su1 += s[nt][0];
            s[nt][1] = __expf(s[nt][1] - nm1); su1 += s[nt][1];
            s[nt][2] = __expf(s[nt][2] - nm2); su2 += s[nt][2];
            s[nt][3] = __expf(s[nt][3] - nm2); su2 += s[nt][3];
        }
        su1 += __shfl_xor_sync(0xffffffffu, su1, 1);
        su1 += __shfl_xor_sync(0xffffffffu, su1, 2);
        su2 += __shfl_xor_sync(0xffffffffu, su2, 1);
        su2 += __shfl_xor_sync(0xffffffffu, su2, 2);
        l1 = l1 * sc1 + su1;  m1 = nm1;
        l2 = l2 * sc2 + su2;  m2 = nm2;
        #pragma unroll
        for (int nt = 0; nt < 8; nt++) {
            o[nt][0] *= sc1; o[nt][1] *= sc1;
            o[nt][2] *= sc2; o[nt][3] *= sc2;
        }

        // ---- stage P (warp-private rows) ----
        {
            uint32_t p1 = sP + (uint32_t)((wid * 16 + lq) * PP + 2 * lc) * 4;
            uint32_t p2 = p1 + (uint32_t)(8 * PP) * 4;
            #pragma unroll
            for (int nt = 0; nt < 8; nt++) {
                asm volatile("st.shared.v2.b32 [%0], {%1, %2};"
                    :: "r"(p1 + nt * 32),
                       "r"(f32_to_tf32(s[nt][0])), "r"(f32_to_tf32(s[nt][1])) : "memory");
                asm volatile("st.shared.v2.b32 [%0], {%1, %2};"
                    :: "r"(p2 + nt * 32),
                       "r"(f32_to_tf32(s[nt][2])), "r"(f32_to_tf32(s[nt][3])) : "memory");
            }
        }
        __syncwarp();

        // ---- O += P V ----
        {
            uint32_t pbase = sP + (uint32_t)((wid * 16 + qm + rq) * PP + qk) * 4;
            #pragma unroll
            for (int ks = 0; ks < 8; ks++) {
                uint32_t pf[4];
                ldsm4(pf, pbase + ks * 32);
                #pragma unroll
                for (int nt2 = 0; nt2 < 4; nt2++) {
                    uint32_t bb[4];
                    ldsm4(bb, sVb + (uint32_t)((nt2 * 16 + brow) * KP +
                                               ks * 8 + bcol) * 4);
                    mma_tf32(o[2 * nt2],     pf, &bb[0]);
                    mma_tf32(o[2 * nt2 + 1], pf, &bb[2]);
                }
            }
        }
    }

    // ---- normalize and write O (tf32-rounded for the Wo GEMM) ----
    const float i1 = 1.f / l1, i2 = 1.f / l2;
    const int b = bh >> 4, h = bh & 15;
    const int row1 = qt * 128 + wid * 16 + lq;
    const size_t base1 = ((size_t)(b * S_LEN + row1)) * DMODEL + h * 64 + 2 * lc;
    const size_t base2 = base1 + (size_t)8 * DMODEL;
    #pragma unroll
    for (int nt = 0; nt < 8; nt++) {
        *(float2*)(g_O + base1 + nt * 8) =
            make_float2(tf32r(o[nt][0] * i1), tf32r(o[nt][1] * i1));
        *(float2*)(g_O + base2 + nt * 8) =
            make_float2(tf32r(o[nt][2] * i2), tf32r(o[nt][3] * i2));
    }
}

// ------------------------- launch -------------------------------------------
extern "C" void kernel_launch(void* const* d_in, const int* in_sizes, int n_in,
                              void* d_out, int out_size)
{
    const float* x  = (const float*)d_in[0];
    const float* Wq = (const float*)d_in[1];
    const float* Wk = (const float*)d_in[2];
    const float* Wv = (const float*)d_in[3];
    const float* Wo = (const float*)d_in[4];
    float* out = (float*)d_out;

    cudaFuncSetAttribute(gemm_kernel,
                         cudaFuncAttributeMaxDynamicSharedMemorySize, GSMEM);
    cudaFuncSetAttribute(flash_kernel,
                         cudaFuncAttributeMaxDynamicSharedMemorySize, FLASH_SMEM);

    prepass_kernel<<<8192, 256>>>((const float4*)x, (const float4*)Wq,
                                  (const float4*)Wk, (const float4*)Wv,
                                  (const float4*)Wo);

    dim3 qkv_grid(24, 32);                   // 3 projections x 8 n-blocks
    gemm_kernel<<<qkv_grid, 256, GSMEM>>>(nullptr, 1);

    dim3 fgrid(32, 16);                      // bh fastest; qt = 15 - y
    flash_kernel<<<fgrid, 256, FLASH_SMEM>>>();

    dim3 ogrid(8, 32);
    gemm_kernel<<<ogrid, 256, GSMEM>>>(out, 0);
}

// round 9
// speedup vs baseline: 4.6057x; 1.0178x over previous
#include <cuda_runtime.h>
#include <math.h>
#include <stdint.h>

#define S_LEN  2048
#define DMODEL 1024
#define NHEAD  16
#define DK     64
#define B_SZ   2
#define M_TOT  (B_SZ * S_LEN)      // 4096
#define BH_TOT (B_SZ * NHEAD)      // 32

// ------------------------- scratch (device globals; no allocs allowed) ------
// Q,K: [b,h,s,dk] tf32 (Q pre-scaled 1/8). V: [b,h,d,s] tf32. O: [b,s,d] tf32.
// X: tf32(x). Wr: tf32(Wq|Wk|Wv|Wo) concatenated.
__device__ float g_Q[(size_t)BH_TOT * S_LEN * DK];
__device__ float g_K[(size_t)BH_TOT * S_LEN * DK];
__device__ float g_V[(size_t)BH_TOT * S_LEN * DK];
__device__ float g_O[(size_t)M_TOT * DMODEL];
__device__ float g_X[(size_t)M_TOT * DMODEL];
__device__ float g_Wr[(size_t)4 * DMODEL * DMODEL];

// ======================= helpers =============================================
__device__ __forceinline__ uint32_t smem_u32(const void* p) {
    uint32_t a;
    asm("{ .reg .u64 t; cvta.to.shared.u64 t, %1; cvt.u32.u64 %0, t; }"
        : "=r"(a) : "l"(p));
    return a;
}
__device__ __forceinline__ uint32_t f32_to_tf32(float f) {
    uint32_t r;
    asm("cvt.rna.tf32.f32 %0, %1;" : "=r"(r) : "f"(f));
    return r;
}
__device__ __forceinline__ float tf32r(float f) {
    return __uint_as_float(f32_to_tf32(f));
}
__device__ __forceinline__ void ldsm4(uint32_t r[4], uint32_t addr) {
    asm volatile("ldmatrix.sync.aligned.m8n8.x4.shared.b16 {%0,%1,%2,%3}, [%4];"
                 : "=r"(r[0]), "=r"(r[1]), "=r"(r[2]), "=r"(r[3]) : "r"(addr));
}
__device__ __forceinline__ void mma_tf32(float d[4], const uint32_t a[4],
                                         const uint32_t b[2]) {
    asm volatile("mma.sync.aligned.m16n8k8.row.col.f32.tf32.tf32.f32 "
                 "{%0,%1,%2,%3}, {%4,%5,%6,%7}, {%8,%9}, {%0,%1,%2,%3};"
                 : "+f"(d[0]), "+f"(d[1]), "+f"(d[2]), "+f"(d[3])
                 : "r"(a[0]), "r"(a[1]), "r"(a[2]), "r"(a[3]),
                   "r"(b[0]), "r"(b[1]));
}
#define CP_ASYNC16(dst, src) \
    asm volatile("cp.async.cg.shared.global [%0], [%1], 16;" \
                 :: "r"(dst), "l"(src) : "memory")
#define CP_COMMIT() asm volatile("cp.async.commit_group;" ::: "memory")
#define CP_WAIT0()  asm volatile("cp.async.wait_group 0;" ::: "memory")
#define CP_WAIT1()  asm volatile("cp.async.wait_group 1;" ::: "memory")

// ======================= pre-pass: round x, W to tf32 ========================
__global__ __launch_bounds__(256) void prepass_kernel(
    const float4* __restrict__ x,  const float4* __restrict__ wq,
    const float4* __restrict__ wk, const float4* __restrict__ wv,
    const float4* __restrict__ wo)
{
    int idx = blockIdx.x * 256 + threadIdx.x;   // 0 .. 2097151
    float4 v; float4* dst;
    if (idx < 1048576) {
        v = x[idx]; dst = (float4*)g_X + idx;
    } else {
        int r = idx - 1048576;
        int which = r >> 18, off = r & 262143;
        const float4* src = (which == 0) ? wq : (which == 1) ? wk
                          : (which == 2) ? wv : wo;
        v = src[off];
        dst = (float4*)g_Wr + ((size_t)which << 18) + off;
    }
    v.x = tf32r(v.x); v.y = tf32r(v.y); v.z = tf32r(v.z); v.w = tf32r(v.w);
    *dst = v;
}

// ======================= tf32 GEMM (cp.async double-buffered) ================
#define PA 36
#define GTILE (128 * PA)
#define GSMEM (4 * GTILE * 4)   // 73728 B

__global__ void __launch_bounds__(256, 2) gemm_kernel(float* __restrict__ out,
                                                      int job)
{
    extern __shared__ float smg[];
    const uint32_t sG = smem_u32(smg);

    const int tid = threadIdx.x;
    const int wid = tid >> 5, lane = tid & 31;
    const int wm = (wid >> 2) * 64;
    const int wn = (wid & 3) * 32;
    const int bm = blockIdx.y * 128;

    int bn, mode;
    const float *Ap, *Wp;
    if (job == 0) {
        Ap = g_O; Wp = g_Wr + 3 * 1048576; mode = 0; bn = blockIdx.x * 128;
    } else {
        int which = blockIdx.x >> 3;
        bn = (blockIdx.x & 7) * 128;
        Ap = g_X; Wp = g_Wr + (size_t)which * 1048576;
        mode = (which == 2) ? 1 : which + 2;   // 0->Q(2), 1->K(3), 2->V(1)
    }

    const int q = lane >> 3, rq = lane & 7;
    const int qm = (q & 1) * 8, qk = (q & 2) * 2;
    const int brow = (lane & 7) + ((lane >> 4) << 3);
    const int bcol = ((lane >> 3) & 1) * 4;

    float acc[4][4][4];
    #pragma unroll
    for (int mt = 0; mt < 4; mt++)
        #pragma unroll
        for (int nt = 0; nt < 4; nt++)
            #pragma unroll
            for (int i = 0; i < 4; i++) acc[mt][nt][i] = 0.f;

    const int cr = tid >> 3, cch = tid & 7;
    {
        uint32_t ab = sG, bb = sG + GTILE * 4;
        uint32_t doff = (uint32_t)(cr * PA + cch * 4) * 4;
        #pragma unroll
        for (int i = 0; i < 4; i++) {
            int r = cr + i * 32;
            CP_ASYNC16(ab + doff + (uint32_t)(i * 32 * PA) * 4,
                       Ap + (size_t)(bm + r) * DMODEL + cch * 4);
            CP_ASYNC16(bb + doff + (uint32_t)(i * 32 * PA) * 4,
                       Wp + (size_t)(bn + r) * DMODEL + cch * 4);
        }
        CP_COMMIT();
    }

    for (int t = 0; t < 32; t++) {
        const int buf = t & 1;
        if (t < 31) {
            int k0 = (t + 1) * 32;
            uint32_t ab = sG + (uint32_t)((buf ^ 1) * 2 * GTILE) * 4;
            uint32_t bb = ab + GTILE * 4;
            uint32_t doff = (uint32_t)(cr * PA + cch * 4) * 4;
            #pragma unroll
            for (int i = 0; i < 4; i++) {
                int r = cr + i * 32;
                CP_ASYNC16(ab + doff + (uint32_t)(i * 32 * PA) * 4,
                           Ap + (size_t)(bm + r) * DMODEL + k0 + cch * 4);
                CP_ASYNC16(bb + doff + (uint32_t)(i * 32 * PA) * 4,
                           Wp + (size_t)(bn + r) * DMODEL + k0 + cch * 4);
            }
            CP_COMMIT();
            CP_WAIT1();
        } else {
            CP_WAIT0();
        }
        __syncthreads();

        const uint32_t aB = sG + (uint32_t)(buf * 2 * GTILE) * 4;
        const uint32_t bB = aB + (uint32_t)GTILE * 4;
        #pragma unroll
        for (int ks = 0; ks < 4; ks++) {
            uint32_t aR[4][4], b0[4], b1[4];
            #pragma unroll
            for (int mt = 0; mt < 4; mt++)
                ldsm4(aR[mt], aB + (uint32_t)((wm + mt * 16 + qm + rq) * PA +
                                              ks * 8 + qk) * 4);
            ldsm4(b0, bB + (uint32_t)((wn + brow) * PA + ks * 8 + bcol) * 4);
            ldsm4(b1, bB + (uint32_t)((wn + 16 + brow) * PA + ks * 8 + bcol) * 4);
            #pragma unroll
            for (int mt = 0; mt < 4; mt++) {
                mma_tf32(acc[mt][0], aR[mt], &b0[0]);
                mma_tf32(acc[mt][1], aR[mt], &b0[2]);
                mma_tf32(acc[mt][2], aR[mt], &b1[0]);
                mma_tf32(acc[mt][3], aR[mt], &b1[2]);
            }
        }
        __syncthreads();
    }

    const float kf = 0.28782313662425573f;
    #pragma unroll
    for (int mt = 0; mt < 4; mt++) {
        #pragma unroll
        for (int nt = 0; nt < 4; nt++) {
            float* a = acc[mt][nt];
            const int col = bn + wn + nt * 8 + 2 * (lane & 3);
            const int rbase = bm + wm + mt * 16 + (lane >> 2);
            if (mode == 0) {
                *(float2*)(out + (size_t)rbase * DMODEL + col) =
                    make_float2(a[0], a[1]);
                *(float2*)(out + (size_t)(rbase + 8) * DMODEL + col) =
                    make_float2(a[2], a[3]);
            } else if (mode == 1) {
                const int h = col >> 6, d = col & 63;
                #pragma unroll
                for (int rr = 0; rr < 2; rr++) {
                    int m = rbase + rr * 8;
                    int b = m >> 11, s = m & 2047;
                    float* base = g_V + ((size_t)(b * NHEAD + h) * DK) * S_LEN;
                    base[(size_t)d * S_LEN + s]       = tf32r(a[rr * 2]);
                    base[(size_t)(d + 1) * S_LEN + s] = tf32r(a[rr * 2 + 1]);
                }
            } else {
                const int h = col >> 6, d = col & 63;
                const float qs = (mode == 2) ? 0.125f : 1.0f;
                float* dst = (mode == 2) ? g_Q : g_K;
                float fr = expf(-(float)(d >> 1) * kf);
                #pragma unroll
                for (int rr = 0; rr < 2; rr++) {
                    int m = rbase + rr * 8;
                    int b = m >> 11, s = m & 2047;
                    float e = a[rr * 2], o = a[rr * 2 + 1];
                    float sn, cs;
                    sincosf((float)s * fr, &sn, &cs);
                    float2 v = make_float2(tf32r((e * cs - o * sn) * qs),
                                           tf32r((e * sn + o * cs) * qs));
                    *(float2*)(dst + ((size_t)(b * NHEAD + h) * S_LEN + s) * DK + d) = v;
                }
            }
        }
    }
}

// ================= causal flash attention, kv-pipelined ======================
// Iter j: softmax(S(j)) [tensor drains PV(j-1)] -> stage P -> S-mma(j+1) -> PV(j).
// Tile t lives in buf t&1; copy(j+2) issued after end-of-iter barrier.
#define KP 68
#define PP 68
#define KV_TILE_F (64 * KP)
#define BUF_F     (2 * KV_TILE_F)
#define FLASH_SMEM ((2 * BUF_F + 128 * PP) * 4)   // 104448 B

__global__ void __launch_bounds__(256, 2) flash_kernel()
{
    extern __shared__ float smf[];
    float* Ps = smf + 2 * BUF_F;
    const uint32_t sK = smem_u32(smf);
    const uint32_t sP = smem_u32(Ps);

    const int qt = 15 - blockIdx.y;     // big tiles first (bh fastest)
    const int bh = blockIdx.x;
    const float* Qp  = g_Q + (size_t)bh * S_LEN * DK;
    const float* Kp  = g_K + (size_t)bh * S_LEN * DK;
    const float* Vtp = g_V + (size_t)bh * S_LEN * DK;   // [d][s]

    const int tid = threadIdx.x;
    const int wid = tid >> 5, lane = tid & 31;
    const int q = lane >> 3, rq = lane & 7;
    const int qm = (q & 1) * 8, qk = (q & 2) * 2;
    const int lq = lane >> 2, lc = lane & 3;
    const int brow = (lane & 7) + ((lane >> 4) << 3);
    const int bcol = ((lane >> 3) & 1) * 4;
    const int cr = tid >> 4, cc = tid & 15;

    const int nkt = 2 * qt + 2;

    // ---- async copy of tile t into buf b ----
    #define COPY_TILE(t, b) do {                                               \
        uint32_t kb = sK + (uint32_t)((b) * BUF_F) * 4;                        \
        uint32_t vb = kb + (uint32_t)KV_TILE_F * 4;                            \
        uint32_t doff = (uint32_t)(cr * KP + cc * 4) * 4;                      \
        const float* Kn = Kp + (size_t)(t) * 64 * DK;                          \
        const float* Vn = Vtp + (size_t)(t) * 64;                              \
        _Pragma("unroll")                                                      \
        for (int i_ = 0; i_ < 4; i_++) {                                       \
            int r_ = cr + i_ * 16;                                             \
            CP_ASYNC16(kb + doff + (uint32_t)(i_ * 16 * KP) * 4,               \
                       Kn + (size_t)r_ * DK + cc * 4);                         \
            CP_ASYNC16(vb + doff + (uint32_t)(i_ * 16 * KP) * 4,               \
                       Vn + (size_t)r_ * S_LEN + cc * 4);                      \
        }                                                                      \
        CP_COMMIT();                                                           \
    } while (0)

    // ---- S-mma from K in buffer b into s ----
    #define S_MMA(b) do {                                                      \
        const uint32_t sKb_ = sK + (uint32_t)((b) * BUF_F) * 4;                \
        _Pragma("unroll")                                                      \
        for (int nt_ = 0; nt_ < 8; nt_++)                                      \
            _Pragma("unroll")                                                  \
            for (int j_ = 0; j_ < 4; j_++) s[nt_][j_] = 0.f;                   \
        _Pragma("unroll")                                                      \
        for (int ks_ = 0; ks_ < 8; ks_++) {                                    \
            _Pragma("unroll")                                                  \
            for (int n2_ = 0; n2_ < 4; n2_++) {                                \
                uint32_t bb_[4];                                               \
                ldsm4(bb_, sKb_ + (uint32_t)((n2_ * 16 + brow) * KP +          \
                                             ks_ * 8 + bcol) * 4);             \
                mma_tf32(s[2 * n2_],     qf[ks_], &bb_[0]);                    \
                mma_tf32(s[2 * n2_ + 1], qf[ks_], &bb_[2]);                    \
            }                                                                  \
        }                                                                      \
    } while (0)

    // ---- prologue: tiles 0 and 1 in flight ----
    COPY_TILE(0, 0);
    COPY_TILE(1, 1);

    // stage Q (already tf32) and build fragments
    #pragma unroll
    for (int i = 0; i < 8; i++) {
        int f = tid + i * 256;
        int r = f >> 4, c = f & 15;
        float4 v = *(const float4*)(Qp + (size_t)(qt * 128 + r) * DK + c * 4);
        *(float4*)&Ps[r * PP + c * 4] = v;
    }
    __syncthreads();
    uint32_t qf[8][4];
    {
        uint32_t base = sP + (uint32_t)((wid * 16 + qm + rq) * PP + qk) * 4;
        #pragma unroll
        for (int ks = 0; ks < 8; ks++) ldsm4(qf[ks], base + ks * 32);
    }

    float m1 = -INFINITY, m2 = -INFINITY, l1 = 0.f, l2 = 0.f;
    float o[8][4];
    #pragma unroll
    for (int nt = 0; nt < 8; nt++)
        #pragma unroll
        for (int j = 0; j < 4; j++) o[nt][j] = 0.f;

    float s[8][4];
    CP_WAIT1();            // tile 0 arrived (tile 1 may still be in flight)
    __syncthreads();
    S_MMA(0);              // S(0)

    for (int j = 0; j < nkt; j++) {
        // ---- causal mask on S(j) ----
        if (j >= 2 * qt) {
            const int row1 = qt * 128 + wid * 16 + lq;
            #pragma unroll
            for (int nt = 0; nt < 8; nt++) {
                int colb = j * 64 + nt * 8 + 2 * lc;
                if (colb     > row1)     s[nt][0] = -INFINITY;
                if (colb + 1 > row1)     s[nt][1] = -INFINITY;
                if (colb     > row1 + 8) s[nt][2] = -INFINITY;
                if (colb + 1 > row1 + 8) s[nt][3] = -INFINITY;
            }
        }

        // ---- online softmax (tensor pipe drains PV(j-1) meanwhile) ----
        float mx1 = -INFINITY, mx2 = -INFINITY;
        #pragma unroll
        for (int nt = 0; nt < 8; nt++) {
            mx1 = fmaxf(mx1, fmaxf(s[nt][0], s[nt][1]));
            mx2 = fmaxf(mx2, fmaxf(s[nt][2], s[nt][3]));
        }
        mx1 = fmaxf(mx1, __shfl_xor_sync(0xffffffffu, mx1, 1));
        mx1 = fmaxf(mx1, __shfl_xor_sync(0xffffffffu, mx1, 2));
        mx2 = fmaxf(mx2, __shfl_xor_sync(0xffffffffu, mx2, 1));
        mx2 = fmaxf(mx2, __shfl_xor_sync(0xffffffffu, mx2, 2));
        const float nm1 = fmaxf(m1, mx1), nm2 = fmaxf(m2, mx2);
        const float sc1 = __expf(m1 - nm1), sc2 = __expf(m2 - nm2);
        float su1 = 0.f, su2 = 0.f;
        #pragma unroll
        for (int nt = 0; nt < 8; nt++) {
            s[nt][0] = __expf(s[nt][0] - nm1); su1 += s[nt][0];
            s[nt][1] = __expf(s[nt][1] - nm1); su1 += s[nt][1];
            s[nt][2] = __expf(s[nt][2] - nm2); su2 += s[nt][2];
            s[nt][3] = __expf(s[nt][3] - nm2); su2 += s[nt][3];
        }
        su1 += __shfl_xor_sync(0xffffffffu, su1, 1);
        su1 += __shfl_xor_sync(0xffffffffu, su1, 2);
        su2 += __shfl_xor_sync(0xffffffffu, su2, 1);
        su2 += __shfl_xor_sync(0xffffffffu, su2, 2);
        l1 = l1 * sc1 + su1;  m1 = nm1;
        l2 = l2 * sc2 + su2;  m2 = nm2;
        #pragma unroll
        for (int nt = 0; nt < 8; nt++) {
            o[nt][0] *= sc1; o[nt][1] *= sc1;
            o[nt][2] *= sc2; o[nt][3] *= sc2;
        }

        // ---- stage P(j) (warp-private rows); frees s ----
        {
            uint32_t p1 = sP + (uint32_t)((wid * 16 + lq) * PP + 2 * lc) * 4;
            uint32_t p2 = p1 + (uint32_t)(8 * PP) * 4;
            #pragma unroll
            for (int nt = 0; nt < 8; nt++) {
                asm volatile("st.shared.v2.b32 [%0], {%1, %2};"
                    :: "r"(p1 + nt * 32),
                       "r"(f32_to_tf32(s[nt][0])), "r"(f32_to_tf32(s[nt][1])) : "memory");
                asm volatile("st.shared.v2.b32 [%0], {%1, %2};"
                    :: "r"(p2 + nt * 32),
                       "r"(f32_to_tf32(s[nt][2])), "r"(f32_to_tf32(s[nt][3])) : "memory");
            }
        }
        __syncwarp();

        // ---- S-mma(j+1) into s (keeps tensor pipe fed through next softmax) --
        if (j + 1 < nkt) {
            CP_WAIT0();          // K(j+1)/V(j+1) arrived
            __syncthreads();     // visible to all warps
            S_MMA((j + 1) & 1);
        }

        // ---- PV(j): O += P(j) * V(j) ----
        {
            const uint32_t sVb = sK + (uint32_t)((j & 1) * BUF_F +
                                                 KV_TILE_F) * 4;
            uint32_t pbase = sP + (uint32_t)((wid * 16 + qm + rq) * PP + qk) * 4;
            #pragma unroll
            for (int ks = 0; ks < 8; ks++) {
                uint32_t pf[4];
                ldsm4(pf, pbase + ks * 32);
                #pragma unroll
                for (int n2 = 0; n2 < 4; n2++) {
                    uint32_t bb[4];
                    ldsm4(bb, sVb + (uint32_t)((n2 * 16 + brow) * KP +
                                               ks * 8 + bcol) * 4);
                    mma_tf32(o[2 * n2],     pf, &bb[0]);
                    mma_tf32(o[2 * n2 + 1], pf, &bb[2]);
                }
            }
        }

        // ---- end of iter: safe to overwrite buf j&1 with tile j+2 ----
        __syncthreads();
        if (j + 2 < nkt) COPY_TILE(j + 2, j & 1);
    }

    // ---- normalize and write O (tf32-rounded for the Wo GEMM) ----
    const float i1 = 1.f / l1, i2 = 1.f / l2;
    const int b = bh >> 4, h = bh & 15;
    const int row1 = qt * 128 + wid * 16 + lq;
    const size_t base1 = ((size_t)(b * S_LEN + row1)) * DMODEL + h * 64 + 2 * lc;
    const size_t base2 = base1 + (size_t)8 * DMODEL;
    #pragma unroll
    for (int nt = 0; nt < 8; nt++) {
        *(float2*)(g_O + base1 + nt * 8) =
            make_float2(tf32r(o[nt][0] * i1), tf32r(o[nt][1] * i1));
        *(float2*)(g_O + base2 + nt * 8) =
            make_float2(tf32r(o[nt][2] * i2), tf32r(o[nt][3] * i2));
    }
    #undef COPY_TILE
    #undef S_MMA
}

// ------------------------- launch -------------------------------------------
extern "C" void kernel_launch(void* const* d_in, const int* in_sizes, int n_in,
                              void* d_out, int out_size)
{
    const float* x  = (const float*)d_in[0];
    const float* Wq = (const float*)d_in[1];
    const float* Wk = (const float*)d_in[2];
    const float* Wv = (const float*)d_in[3];
    const float* Wo = (const float*)d_in[4];
    float* out = (float*)d_out;

    cudaFuncSetAttribute(gemm_kernel,
                         cudaFuncAttributeMaxDynamicSharedMemorySize, GSMEM);
    cudaFuncSetAttribute(flash_kernel,
                         cudaFuncAttributeMaxDynamicSharedMemorySize, FLASH_SMEM);

    prepass_kernel<<<8192, 256>>>((const float4*)x, (const float4*)Wq,
                                  (const float4*)Wk, (const float4*)Wv,
                                  (const float4*)Wo);

    dim3 qkv_grid(24, 32);                   // 3 projections x 8 n-blocks
    gemm_kernel<<<qkv_grid, 256, GSMEM>>>(nullptr, 1);

    dim3 fgrid(32, 16);                      // bh fastest; qt = 15 - y
    flash_kernel<<<fgrid, 256, FLASH_SMEM>>>();

    dim3 ogrid(8, 32);
    gemm_kernel<<<ogrid, 256, GSMEM>>>(out, 0);
}